// round 12
// baseline (speedup 1.0000x reference)
#include <cuda_runtime.h>
#include <cuda_bf16.h>
#include <math_constants.h>
#include <cstdint>

// Problem constants
#define Bdim 4
#define Sdim 1024
#define Ddim 2048
#define Hdim 16
#define DHdim 128
#define MROWS (Bdim * Sdim)   // 4096

static const float SCALE_F = 11.313708498984761f;  // sqrt(128)

// tcgen05 is arch-specific ("a") — only compile it on the sm_103a pass.
#if defined(__CUDA_ARCH_FEAT_SM103_ALL) || \
    (defined(__CUDA_ARCH_SPECIFIC__) && defined(__CUDA_ARCH__) && (__CUDA_ARCH__ == 1030))
#define GEMM_TCGEN05 1
#endif

// ---------------------------------------------------------------------------
// Scratch (allocation-free rule: __device__ globals)
// ---------------------------------------------------------------------------
__device__ __align__(256) __nv_bfloat16 g_xhi[MROWS * Ddim];
__device__ __align__(256) __nv_bfloat16 g_xlo[MROWS * Ddim];
__device__ __align__(256) __nv_bfloat16 g_whi[4][Ddim * Ddim];
__device__ __align__(256) __nv_bfloat16 g_wlo[4][Ddim * Ddim];
__device__ __align__(256) __nv_bfloat16 g_qkvhi[3][MROWS * Ddim];
__device__ __align__(256) __nv_bfloat16 g_qkvlo[3][MROWS * Ddim];
__device__ __align__(256) __nv_bfloat16 g_chi[MROWS * Ddim];
__device__ __align__(256) __nv_bfloat16 g_clo[MROWS * Ddim];

// ---------------------------------------------------------------------------
// Helpers
// ---------------------------------------------------------------------------
__device__ __forceinline__ uint32_t smem_u32(const void* p) {
    uint32_t a;
    asm("{ .reg .u64 t; cvta.to.shared.u64 t, %1; cvt.u32.u64 %0, t; }"
        : "=r"(a) : "l"(p));
    return a;
}

__device__ __forceinline__ void cp16(uint32_t dst, const void* src) {
    asm volatile("cp.async.cg.shared.global [%0], [%1], 16;"
                 :: "r"(dst), "l"(src));
}

#define LDSM4(r, addr) \
    asm volatile("ldmatrix.sync.aligned.m8n8.x4.shared.b16 {%0,%1,%2,%3}, [%4];" \
        : "=r"((r)[0]), "=r"((r)[1]), "=r"((r)[2]), "=r"((r)[3]) : "r"(addr))

#define LDSM4T(r, addr) \
    asm volatile("ldmatrix.sync.aligned.m8n8.x4.trans.shared.b16 {%0,%1,%2,%3}, [%4];" \
        : "=r"((r)[0]), "=r"((r)[1]), "=r"((r)[2]), "=r"((r)[3]) : "r"(addr))

#define MMA_BF16(d, a, b) \
    asm volatile("mma.sync.aligned.m16n8k16.row.col.f32.bf16.bf16.f32 " \
        "{%0,%1,%2,%3}, {%4,%5,%6,%7}, {%8,%9}, {%0,%1,%2,%3};" \
        : "+f"((d)[0]), "+f"((d)[1]), "+f"((d)[2]), "+f"((d)[3]) \
        : "r"((a)[0]), "r"((a)[1]), "r"((a)[2]), "r"((a)[3]), \
          "r"((b)[0]), "r"((b)[1]))

#define STS128(addr, r0, r1, r2, r3) \
    asm volatile("st.shared.v4.b32 [%0], {%1,%2,%3,%4};" \
        :: "r"(addr), "r"(r0), "r"(r1), "r"(r2), "r"(r3) : "memory")

// split f32 pair -> packed bf16x2 hi + bf16x2 lo
__device__ __forceinline__ void split_pack2(float x, float y,
                                            uint32_t& hi, uint32_t& lo) {
    __nv_bfloat16 bx = __float2bfloat16_rn(x), by = __float2bfloat16_rn(y);
    __nv_bfloat162 h; h.x = bx; h.y = by;
    hi = *(uint32_t*)&h;
    __nv_bfloat162 l;
    l.x = __float2bfloat16_rn(x - __bfloat162float(bx));
    l.y = __float2bfloat16_rn(y - __bfloat162float(by));
    lo = *(uint32_t*)&l;
}

__device__ __forceinline__ void store_split2(__nv_bfloat16* ph, __nv_bfloat16* pl,
                                             float x, float y) {
    uint32_t hi, lo;
    split_pack2(x, y, hi, lo);
    *(uint32_t*)ph = hi;
    *(uint32_t*)pl = lo;
}

// ---------------------------------------------------------------------------
// Fused split: x + all 4 weights in ONE launch; 8 floats per thread.
// ---------------------------------------------------------------------------
#define XN8 (MROWS * Ddim / 8)      // 2^20
#define WN8 (Ddim * Ddim / 8)       // 2^19

__global__ __launch_bounds__(256) void split_all(
    const float* __restrict__ x,
    const float* __restrict__ W0, const float* __restrict__ W1,
    const float* __restrict__ W2, const float* __restrict__ W3,
    __nv_bfloat16* __restrict__ xhi, __nv_bfloat16* __restrict__ xlo,
    __nv_bfloat16* __restrict__ whi, __nv_bfloat16* __restrict__ wlo)
{
    int i = blockIdx.x * 256 + threadIdx.x;   // unit = 8 floats
    const float* in;
    __nv_bfloat16 *hi, *lo;
    int off;
    if (i < XN8) {
        in = x; hi = xhi; lo = xlo; off = i;
    } else {
        int t = i - XN8;
        int r = t >> 19;            // / WN8
        off = t & (WN8 - 1);
        in = (r == 0) ? W0 : (r == 1) ? W1 : (r == 2) ? W2 : W3;
        hi = whi + (size_t)r * (Ddim * Ddim);
        lo = wlo + (size_t)r * (Ddim * Ddim);
    }
    const float4* p4 = (const float4*)in + 2 * (size_t)off;
    float4 v0 = p4[0], v1 = p4[1];
    uint32_t h[4], l[4];
    split_pack2(v0.x, v0.y, h[0], l[0]);
    split_pack2(v0.z, v0.w, h[1], l[1]);
    split_pack2(v1.x, v1.y, h[2], l[2]);
    split_pack2(v1.z, v1.w, h[3], l[3]);
    ((uint4*)hi)[off] = make_uint4(h[0], h[1], h[2], h[3]);
    ((uint4*)lo)[off] = make_uint4(l[0], l[1], l[2], l[3]);
}

// ---------------------------------------------------------------------------
// Unified bf16x2-split GEMM (validated R9-R11): 256x256 tile tcgen05 path +
// mma.sync fallback.  C ~= Ahi*Bhi + Ahi*Blo + Alo*Bhi.
// ---------------------------------------------------------------------------
#define TSTAGES 3
#define TKC 32
#define TOP_BUF 16384                          // 256 rows x 64B per operand buf
#define TSTAGE_BYTES (4 * TOP_BUF)             // 64KB
#define TCTRL 1024
#define GSMEM_UNIFIED (TCTRL + TSTAGES * TSTAGE_BYTES)   // 197632
#define TIDESC 0x8400490u
#define TMEM_COLS_ALLOC 512u

#define MSTAGES 4
#define MKC 32
#define MBUF 8192
#define MSTAGE_BYTES (4 * MBUF)

__device__ __forceinline__ uint32_t soff(int r, int c) {
    return (uint32_t)(r * 64 + ((c ^ ((r >> 1) & 3)) << 4));
}

__device__ __forceinline__ void ld_chunk(uint32_t stg,
    const __nv_bfloat16* a1, const __nv_bfloat16* a2,
    const __nv_bfloat16* b1, const __nv_bfloat16* b2, int K, int tid)
{
    const __nv_bfloat16* gp[4] = { a1, a2, b1, b2 };
#pragma unroll
    for (int b = 0; b < 4; b++) {
        uint32_t base = stg + b * MBUF;
#pragma unroll
        for (int i = 0; i < 2; i++) {
            int u = i * 256 + tid;
            int r = u >> 2, c = u & 3;
            cp16(base + soff(r, c), gp[b] + (size_t)r * K + c * 8);
        }
    }
    asm volatile("cp.async.commit_group;" ::: "memory");
}

#ifdef GEMM_TCGEN05
#define SW64(x) ((x) ^ (((x) >> 3) & 0x30))
#define SW128(x) ((x) ^ (((x) >> 3) & 0x70))

__device__ __forceinline__ uint64_t mk_desc64(uint32_t addr) {
    return ((uint64_t)4 << 61) | ((uint64_t)1 << 46) | ((uint64_t)32 << 32)
         | ((uint64_t)1 << 16) | ((addr >> 4) & 0x3FFF);
}
__device__ __forceinline__ uint64_t mk_desc128(uint32_t addr) {
    return ((uint64_t)2 << 61) | ((uint64_t)1 << 46) | ((uint64_t)64 << 32)
         | ((uint64_t)1 << 16) | ((addr >> 4) & 0x3FFF);
}

__device__ __forceinline__ uint32_t elect1() {
    uint32_t p;
    asm volatile("{ .reg .pred p; elect.sync _|p, 0xFFFFFFFF; selp.b32 %0, 1, 0, p; }"
                 : "=r"(p));
    return p;
}

__device__ __forceinline__ void mbar_wait(uint32_t addr, int parity) {
    asm volatile(
        "{\n\t"
        ".reg .pred P1;\n\t"
        "WAIT_LOOP_%=:\n\t"
        "mbarrier.try_wait.parity.acquire.cta.shared::cta.b64 P1, [%0], %1, 0x989680;\n\t"
        "@P1 bra.uni WAIT_DONE_%=;\n\t"
        "bra.uni WAIT_LOOP_%=;\n\t"
        "WAIT_DONE_%=:\n\t"
        "}"
        :: "r"(addr), "r"((uint32_t)parity) : "memory");
}

#define TCLD_X32(r, tmem_addr) \
    asm volatile( \
        "tcgen05.ld.sync.aligned.32x32b.x32.b32 " \
        "{%0, %1, %2, %3, %4, %5, %6, %7, " \
        " %8, %9, %10, %11, %12, %13, %14, %15, " \
        " %16, %17, %18, %19, %20, %21, %22, %23, " \
        " %24, %25, %26, %27, %28, %29, %30, %31}, [%32];" \
        : "=r"((r)[0]),  "=r"((r)[1]),  "=r"((r)[2]),  "=r"((r)[3]), \
          "=r"((r)[4]),  "=r"((r)[5]),  "=r"((r)[6]),  "=r"((r)[7]), \
          "=r"((r)[8]),  "=r"((r)[9]),  "=r"((r)[10]), "=r"((r)[11]), \
          "=r"((r)[12]), "=r"((r)[13]), "=r"((r)[14]), "=r"((r)[15]), \
          "=r"((r)[16]), "=r"((r)[17]), "=r"((r)[18]), "=r"((r)[19]), \
          "=r"((r)[20]), "=r"((r)[21]), "=r"((r)[22]), "=r"((r)[23]), \
          "=r"((r)[24]), "=r"((r)[25]), "=r"((r)[26]), "=r"((r)[27]), \
          "=r"((r)[28]), "=r"((r)[29]), "=r"((r)[30]), "=r"((r)[31]) \
        : "r"(tmem_addr))

#define TCLD_X16(r, tmem_addr) \
    asm volatile( \
        "tcgen05.ld.sync.aligned.32x32b.x16.b32 " \
        "{%0, %1, %2, %3, %4, %5, %6, %7, " \
        " %8, %9, %10, %11, %12, %13, %14, %15}, [%16];" \
        : "=r"((r)[0]),  "=r"((r)[1]),  "=r"((r)[2]),  "=r"((r)[3]), \
          "=r"((r)[4]),  "=r"((r)[5]),  "=r"((r)[6]),  "=r"((r)[7]), \
          "=r"((r)[8]),  "=r"((r)[9]),  "=r"((r)[10]), "=r"((r)[11]), \
          "=r"((r)[12]), "=r"((r)[13]), "=r"((r)[14]), "=r"((r)[15]) \
        : "r"(tmem_addr))

#define TCMMA(dtm, adesc, bdesc, idesc, en) \
    asm volatile( \
        "{ .reg .pred pp;\n\t" \
        "setp.ne.u32 pp, %4, 0;\n\t" \
        "tcgen05.mma.cta_group::1.kind::f16 [%0], %1, %2, %3, " \
        "{%5, %5, %5, %5}, pp; }\n" \
        :: "r"(dtm), "l"(adesc), "l"(bdesc), "r"(idesc), "r"(en), "r"(0u) \
        : "memory")

__device__ __forceinline__ void ld_chunk_tc(uint32_t stg,
    const __nv_bfloat16* a1, const __nv_bfloat16* a2,
    const __nv_bfloat16* b1, const __nv_bfloat16* b2, int tid)
{
    const __nv_bfloat16* gp[4] = { a1, a2, b1, b2 };
#pragma unroll
    for (int b = 0; b < 4; b++) {
        uint32_t base = stg + b * TOP_BUF;
#pragma unroll
        for (int it = 0; it < 4; it++) {
            int u = it * 256 + tid;
            int r = u >> 2, c16 = u & 3;
            cp16(base + SW64(r * 64 + c16 * 16),
                 gp[b] + (size_t)r * Ddim + c16 * 8);
        }
    }
    asm volatile("cp.async.commit_group;" ::: "memory");
}
#endif  // GEMM_TCGEN05

__global__ __launch_bounds__(256, 1) void gemm_any(
    const __nv_bfloat16* __restrict__ Ahi, const __nv_bfloat16* __restrict__ Alo,
    const __nv_bfloat16* __restrict__ BhiBase, const __nv_bfloat16* __restrict__ BloBase,
    size_t bStride, __nv_bfloat16* ChB, __nv_bfloat16* ClB, size_t cStride,
    float* Cf, int M, int N, int K)
{
    extern __shared__ __align__(1024) char smem[];
    const uint32_t sb = smem_u32(smem);
    const int tid = threadIdx.x, warp = tid >> 5, lane = tid & 31;
    const int z = blockIdx.z;

#ifdef GEMM_TCGEN05
    const int bm = blockIdx.y * 256;
    const int bn = blockIdx.x * 256;
    const __nv_bfloat16* Abh = Ahi + (size_t)bm * K;
    const __nv_bfloat16* Abl = Alo + (size_t)bm * K;
    const __nv_bfloat16* Bbh = BhiBase + (size_t)z * bStride + (size_t)bn * K;
    const __nv_bfloat16* Bbl = BloBase + (size_t)z * bStride + (size_t)bn * K;
    const int nchunk = K / TKC;   // 64

    if (warp == 0)
        asm volatile("tcgen05.alloc.cta_group::1.sync.aligned.shared::cta.b32 [%0], %1;"
                     :: "r"(sb), "r"(TMEM_COLS_ALLOC) : "memory");
    if (tid == 0) {
#pragma unroll
        for (int s = 0; s < TSTAGES; s++)
            asm volatile("mbarrier.init.shared.b64 [%0], 1;"
                         :: "r"(sb + 8 + 8 * s) : "memory");
    }
    __syncthreads();
    uint32_t tmem;
    asm volatile("ld.shared.b32 %0, [%1];" : "=r"(tmem) : "r"(sb));

    ld_chunk_tc(sb + TCTRL, Abh, Abl, Bbh, Bbl, tid);
    ld_chunk_tc(sb + TCTRL + TSTAGE_BYTES, Abh + TKC, Abl + TKC,
                Bbh + TKC, Bbl + TKC, tid);

    int ph[TSTAGES] = { 0, 0, 0 };

    for (int i = 0; i < nchunk; i++) {
        const int s = i % TSTAGES;
        if (i < nchunk - 1) { asm volatile("cp.async.wait_group 1;" ::: "memory"); }
        else                { asm volatile("cp.async.wait_group 0;" ::: "memory"); }
        __syncthreads();
        asm volatile("fence.proxy.async.shared::cta;" ::: "memory");

        if (warp == 0 && elect1()) {
            const uint32_t stg = sb + TCTRL + s * TSTAGE_BYTES;
            uint64_t dAh = mk_desc64(stg);
            uint64_t dAl = mk_desc64(stg + TOP_BUF);
            uint64_t dBh = mk_desc64(stg + 2 * TOP_BUF);
            uint64_t dBl = mk_desc64(stg + 3 * TOP_BUF);
            uint64_t ad[3] = { dAh, dAh, dAl };
            uint64_t bd[3] = { dBh, dBl, dBh };
#pragma unroll
            for (int p = 0; p < 3; p++)
#pragma unroll
                for (int k = 0; k < 2; k++) {
                    uint32_t en = (i == 0 && p == 0 && k == 0) ? 0u : 1u;
#pragma unroll
                    for (int mt = 0; mt < 2; mt++)
                        TCMMA(tmem + mt * 256, ad[p] + k * 2 + mt * 512,
                              bd[p] + k * 2, TIDESC, en);
                }
            asm volatile(
                "tcgen05.commit.cta_group::1.mbarrier::arrive::one.shared::cluster.b64 [%0];"
                :: "r"(sb + 8 + 8 * s) : "memory");
        }

        const int j = i + 2;
        if (j < nchunk) {
            const int sj = j % TSTAGES;
            if (i >= 1) {
                mbar_wait(sb + 8 + 8 * sj, ph[sj]);
                ph[sj] ^= 1;
            }
            ld_chunk_tc(sb + TCTRL + sj * TSTAGE_BYTES,
                        Abh + (size_t)j * TKC, Abl + (size_t)j * TKC,
                        Bbh + (size_t)j * TKC, Bbl + (size_t)j * TKC, tid);
        }
    }

    const int sf = (nchunk - 1) % TSTAGES;
    mbar_wait(sb + 8 + 8 * sf, ph[sf]);
    asm volatile("tcgen05.fence::after_thread_sync;" ::: "memory");
    __syncthreads();

    {
        const uint32_t acc = tmem + (uint32_t)(warp >> 2) * 256;
        const int mrow_base = bm + (warp >> 2) * 128 + (warp & 3) * 32;
        float* tr = (float*)(smem + TCTRL) + warp * (32 * 33);
#pragma unroll
        for (int cb = 0; cb < 8; cb++) {
            uint32_t dreg[32];
            TCLD_X32(dreg, acc + cb * 32);
            asm volatile("tcgen05.wait::ld.sync.aligned;" ::: "memory");
#pragma unroll
            for (int c = 0; c < 32; c++)
                tr[lane * 33 + c] = __uint_as_float(dreg[c]);
            __syncwarp();
#pragma unroll
            for (int t = 0; t < 8; t++) {
                int idx = t * 32 + lane;
                int r = idx >> 3;
                int c4 = (idx & 7) * 4;
                int grow = mrow_base + r;
                int gcol = bn + cb * 32 + c4;
                float v0 = tr[r * 33 + c4],     v1 = tr[r * 33 + c4 + 1];
                float v2 = tr[r * 33 + c4 + 2], v3 = tr[r * 33 + c4 + 3];
                if (Cf) {
                    *(float4*)&Cf[(size_t)grow * N + gcol] =
                        make_float4(v0, v1, v2, v3);
                } else {
                    __nv_bfloat16* Ch = ChB + (size_t)z * cStride;
                    __nv_bfloat16* Cl = ClB + (size_t)z * cStride;
                    store_split2(&Ch[(size_t)grow * N + gcol],
                                 &Cl[(size_t)grow * N + gcol], v0, v1);
                    store_split2(&Ch[(size_t)grow * N + gcol + 2],
                                 &Cl[(size_t)grow * N + gcol + 2], v2, v3);
                }
            }
            __syncwarp();
        }
    }

    asm volatile("tcgen05.fence::before_thread_sync;" ::: "memory");
    __syncthreads();
    if (warp == 0) {
        asm volatile("tcgen05.relinquish_alloc_permit.cta_group::1.sync.aligned;");
        asm volatile("tcgen05.dealloc.cta_group::1.sync.aligned.b32 %0, %1;"
                     :: "r"(tmem), "r"(TMEM_COLS_ALLOC));
    }

#else
    for (int mm = 0; mm < 2; mm++)
    for (int nn = 0; nn < 2; nn++) {
        const int bmq = blockIdx.y * 256 + mm * 128;
        const int bn = blockIdx.x * 256 + nn * 128;
        const __nv_bfloat16* Abh = Ahi + (size_t)bmq * K;
        const __nv_bfloat16* Abl = Alo + (size_t)bmq * K;
        const __nv_bfloat16* Bbh = BhiBase + (size_t)z * bStride + (size_t)bn * K;
        const __nv_bfloat16* Bbl = BloBase + (size_t)z * bStride + (size_t)bn * K;

        float acc[4][4][4];
#pragma unroll
        for (int mt = 0; mt < 4; mt++)
#pragma unroll
            for (int nt = 0; nt < 4; nt++)
#pragma unroll
                for (int q = 0; q < 4; q++) acc[mt][nt][q] = 0.0f;

        const int nchunk = K / MKC;
        __syncthreads();
#pragma unroll
        for (int s = 0; s < MSTAGES - 1; s++)
            ld_chunk(sb + s * MSTAGE_BYTES, Abh + s * MKC, Abl + s * MKC,
                     Bbh + s * MKC, Bbl + s * MKC, K, tid);

        const int arow_base = (warp >> 2) * 64;
        const int brow_base = (warp & 3) * 32;

        for (int i = 0; i < nchunk; i++) {
            asm volatile("cp.async.wait_group %0;" :: "n"(MSTAGES - 2) : "memory");
            __syncthreads();
            const int j = i + MSTAGES - 1;
            if (j < nchunk)
                ld_chunk(sb + (j & (MSTAGES - 1)) * MSTAGE_BYTES,
                         Abh + j * MKC, Abl + j * MKC, Bbh + j * MKC, Bbl + j * MKC,
                         K, tid);
            const uint32_t stg = sb + (i & (MSTAGES - 1)) * MSTAGE_BYTES;
#pragma unroll
            for (int s = 0; s < 2; s++) {
                uint32_t ah[4][4], al[4][4], bh[2][4], bl[2][4];
#pragma unroll
                for (int mt = 0; mt < 4; mt++) {
                    int row = arow_base + mt * 16 + (lane & 15);
                    int ch  = s * 2 + (lane >> 4);
                    uint32_t ad = stg + soff(row, ch);
                    LDSM4(ah[mt], ad);
                    LDSM4(al[mt], ad + MBUF);
                }
#pragma unroll
                for (int nt2 = 0; nt2 < 2; nt2++) {
                    int row = brow_base + nt2 * 16 + (lane & 7) + ((lane >> 4) << 3);
                    int ch  = s * 2 + ((lane >> 3) & 1);
                    uint32_t bd = stg + 2 * MBUF + soff(row, ch);
                    LDSM4(bh[nt2], bd);
                    LDSM4(bl[nt2], bd + MBUF);
                }
#pragma unroll
                for (int mt = 0; mt < 4; mt++)
#pragma unroll
                    for (int nt = 0; nt < 4; nt++) {
                        uint32_t* bH = &bh[nt >> 1][(nt & 1) * 2];
                        uint32_t* bL = &bl[nt >> 1][(nt & 1) * 2];
                        MMA_BF16(acc[mt][nt], ah[mt], bH);
                        MMA_BF16(acc[mt][nt], ah[mt], bL);
                        MMA_BF16(acc[mt][nt], al[mt], bH);
                    }
            }
        }

        const int crow0 = bmq + arow_base;
        const int ccol0 = bn + brow_base;
        if (Cf) {
#pragma unroll
            for (int mt = 0; mt < 4; mt++)
#pragma unroll
                for (int nt = 0; nt < 4; nt++) {
                    int r0 = crow0 + mt * 16 + (lane >> 2);
                    int c0 = ccol0 + nt * 8 + (lane & 3) * 2;
                    *(float2*)&Cf[(size_t)r0 * N + c0] =
                        make_float2(acc[mt][nt][0], acc[mt][nt][1]);
                    *(float2*)&Cf[(size_t)(r0 + 8) * N + c0] =
                        make_float2(acc[mt][nt][2], acc[mt][nt][3]);
                }
        } else {
            __nv_bfloat16* Ch = ChB + (size_t)z * cStride;
            __nv_bfloat16* Cl = ClB + (size_t)z * cStride;
#pragma unroll
            for (int mt = 0; mt < 4; mt++)
#pragma unroll
                for (int nt = 0; nt < 4; nt++) {
                    int r0 = crow0 + mt * 16 + (lane >> 2);
                    int c0 = ccol0 + nt * 8 + (lane & 3) * 2;
                    store_split2(&Ch[(size_t)r0 * N + c0], &Cl[(size_t)r0 * N + c0],
                                 acc[mt][nt][0], acc[mt][nt][1]);
                    store_split2(&Ch[(size_t)(r0 + 8) * N + c0],
                                 &Cl[(size_t)(r0 + 8) * N + c0],
                                 acc[mt][nt][2], acc[mt][nt][3]);
                }
        }
        __syncthreads();
    }
#endif  // GEMM_TCGEN05
}

// ---------------------------------------------------------------------------
// Causal flash attention.
// sm_103a path: QK^T on tcgen05 + two-pass TMEM softmax (low reg pressure),
// PV on mma.sync with register accumulators, P via smem.
// qt is REVERSED across blockIdx.x so long CTAs start first (LPT schedule).
// ---------------------------------------------------------------------------
#define SOFF2(r, c) ((uint32_t)((r) * 256 + ((((c) ^ ((r) & 7))) << 4)))
#define APSW(r, c)  ((uint32_t)((r) * 128 + ((((c) ^ ((r) & 7))) << 4)))

// tc-path smem map
#define ASM_QH 1024
#define ASM_QL (ASM_QH + 32768)     // 33792
#define ASM_PH (ASM_QL + 32768)     // 66560
#define ASM_PL (ASM_PH + 16384)     // 82944
#define ASM_AL (ASM_PL + 16384)     // 99328  (128 floats)
#define ASM_KV 100352
#define ASM_KV_STAGE 65536          // Kh 16K | Kl 16K | Vh 16K | Vl 16K
#define ASMEM_TOTAL (ASM_KV + 2 * ASM_KV_STAGE)   // 231424
#define AIDESC 0x8100490u           // kind::f16, F32, bf16, M=128, N=64

#ifdef GEMM_TCGEN05
__device__ __forceinline__ void atc_load_q(uint32_t sbq,
    const __nv_bfloat16* qh, const __nv_bfloat16* ql, int tid)
{
    const __nv_bfloat16* g[2] = { qh, ql };
#pragma unroll
    for (int hl = 0; hl < 2; hl++)
#pragma unroll
        for (int d = 0; d < 2; d++)
#pragma unroll
            for (int it = 0; it < 4; it++) {
                int u = it * 256 + tid;       // 0..1023
                int r = u >> 3, c = u & 7;
                cp16(sbq + hl * 32768 + d * 16384 + SW128(r * 128 + c * 16),
                     g[hl] + (size_t)r * Ddim + d * 64 + c * 8);
            }
}

__device__ __forceinline__ void atc_load_kv(uint32_t kv,
    const __nv_bfloat16* kh, const __nv_bfloat16* kl,
    const __nv_bfloat16* vh, const __nv_bfloat16* vl, int k0, int tid)
{
    const __nv_bfloat16* gk[2] = { kh, kl };
#pragma unroll
    for (int hl = 0; hl < 2; hl++)
#pragma unroll
        for (int d = 0; d < 2; d++)
#pragma unroll
            for (int it = 0; it < 2; it++) {
                int u = it * 256 + tid;       // 0..511
                int r = u >> 3, c = u & 7;
                cp16(kv + hl * 16384 + d * 8192 + SW128(r * 128 + c * 16),
                     gk[hl] + (size_t)(k0 + r) * Ddim + d * 64 + c * 8);
            }
    const __nv_bfloat16* gv[2] = { vh, vl };
#pragma unroll
    for (int hl = 0; hl < 2; hl++)
#pragma unroll
        for (int it = 0; it < 4; it++) {
            int u = it * 256 + tid;           // 0..1023
            int r = u >> 4, c = u & 15;
            cp16(kv + 32768 + hl * 16384 + SOFF2(r, c),
                 gv[hl] + (size_t)(k0 + r) * Ddim + c * 8);
        }
    asm volatile("cp.async.commit_group;" ::: "memory");
}
#endif

__global__ __launch_bounds__(256, 1) void attn_any(
    const __nv_bfloat16* __restrict__ Qhi, const __nv_bfloat16* __restrict__ Qlo,
    const __nv_bfloat16* __restrict__ Khi, const __nv_bfloat16* __restrict__ Klo,
    const __nv_bfloat16* __restrict__ Vhi, const __nv_bfloat16* __restrict__ Vlo,
    __nv_bfloat16* __restrict__ Chi, __nv_bfloat16* __restrict__ Clo)
{
    extern __shared__ __align__(1024) char smem[];
    const uint32_t sb = smem_u32(smem);
    const int tid = threadIdx.x, warp = tid >> 5, lane = tid & 31;
    const int qt = (int)gridDim.x - 1 - (int)blockIdx.x;   // LPT: long CTAs first
    const int b = blockIdx.y >> 4, h = blockIdx.y & 15;
    const int q0 = qt * 128;
    const int jmax = 2 * qt + 1;

    const size_t rowbase = ((size_t)b * Sdim) * Ddim + (size_t)h * DHdim;
    const __nv_bfloat16* qh_g = Qhi + rowbase + (size_t)q0 * Ddim;
    const __nv_bfloat16* ql_g = Qlo + rowbase + (size_t)q0 * Ddim;
    const __nv_bfloat16* kh_g = Khi + rowbase;
    const __nv_bfloat16* kl_g = Klo + rowbase;
    const __nv_bfloat16* vh_g = Vhi + rowbase;
    const __nv_bfloat16* vl_g = Vlo + rowbase;

#ifdef GEMM_TCGEN05
    // =====================================================================
    // tcgen05 QK^T + mma.sync PV, two-pass TMEM softmax
    // =====================================================================
    float* alphaArr = (float*)(smem + ASM_AL);

    if (warp == 0)
        asm volatile("tcgen05.alloc.cta_group::1.sync.aligned.shared::cta.b32 [%0], %1;"
                     :: "r"(sb), "r"(128u) : "memory");
    if (tid == 0) {
        asm volatile("mbarrier.init.shared.b64 [%0], 1;" :: "r"(sb + 8) : "memory");
        asm volatile("mbarrier.init.shared.b64 [%0], 1;" :: "r"(sb + 16) : "memory");
    }
    atc_load_q(sb + ASM_QH, qh_g, ql_g, tid);
    atc_load_kv(sb + ASM_KV, kh_g, kl_g, vh_g, vl_g, 0, tid);
    atc_load_kv(sb + ASM_KV + ASM_KV_STAGE, kh_g, kl_g, vh_g, vl_g, 64, tid);
    __syncthreads();
    uint32_t tmem;
    asm volatile("ld.shared.b32 %0, [%1];" : "=r"(tmem) : "r"(sb));

    asm volatile("cp.async.wait_group 1;" ::: "memory");
    __syncthreads();
    asm volatile("fence.proxy.async.shared::cta;" ::: "memory");

    // issue S_0 (warp 4)
    if (warp == 4 && elect1()) {
        const uint32_t kv0 = sb + ASM_KV;
        uint64_t aoff[3] = { 0, 0, 32768 };
        uint64_t boff[3] = { 0, 16384, 0 };
#pragma unroll
        for (int p = 0; p < 3; p++)
#pragma unroll
            for (int k = 0; k < 8; k++) {
                int d = k >> 2, kk = k & 3;
                uint64_t ad = mk_desc128(sb + ASM_QH + (uint32_t)aoff[p] + d * 16384) + kk * 2;
                uint64_t bd = mk_desc128(kv0 + (uint32_t)boff[p] + d * 8192) + kk * 2;
                TCMMA(tmem, ad, bd, AIDESC, (p == 0 && k == 0) ? 0u : 1u);
            }
        asm volatile(
            "tcgen05.commit.cta_group::1.mbarrier::arrive::one.shared::cluster.b64 [%0];"
            :: "r"(sb + 8) : "memory");
    }

    float oacc[16][4];
#pragma unroll
    for (int nt = 0; nt < 16; nt++)
#pragma unroll
        for (int e = 0; e < 4; e++) oacc[nt][e] = 0.0f;
    float m_prev = -CUDART_INF_F, l_run = 0.0f;
    const int qrow = (warp & 3) * 32 + lane;   // softmax row for warps 0-3
    const int arow = warp * 16;                // PV rows for all warps
    int phA[2] = { 0, 0 };

    for (int j = 0; j <= jmax; j++) {
        const int scur = j & 1;
        const int k0 = j * 64;
        const uint32_t kvs = sb + ASM_KV + (uint32_t)scur * ASM_KV_STAGE;
        const int grow = q0 + qrow;
        const bool needmask = (j >= 2 * qt);

        // 1. wait S_j
        mbar_wait(sb + 8 + 8 * scur, phA[scur]);
        phA[scur] ^= 1;

        // 2. pass 1 (warps 0-3): row max via 2x LDTM.x32, regs reused
        float m_new = 0.0f, alpha = 0.0f;
        if (warp < 4) {
            asm volatile("tcgen05.fence::after_thread_sync;" ::: "memory");
            float mx = -CUDART_INF_F;
            uint32_t sr[32];
#pragma unroll
            for (int hf = 0; hf < 2; hf++) {
                TCLD_X32(sr, tmem + scur * 64 + hf * 32);
                asm volatile("tcgen05.wait::ld.sync.aligned;" ::: "memory");
#pragma unroll
                for (int c = 0; c < 32; c++) {
                    float v = __uint_as_float(sr[c]) * SCALE_F;
                    if (needmask && (k0 + hf * 32 + c > grow)) v = -CUDART_INF_F;
                    mx = fmaxf(mx, v);
                }
            }
            m_new = fmaxf(m_prev, mx);
            alpha = __expf(m_prev - m_new);
        }

        // 3. issue S_{j+1} (warp 4) after KV_{j+1} resident (single barrier)
        if (j < jmax) {
            asm volatile("cp.async.wait_group 0;" ::: "memory");
            __syncthreads();
            asm volatile("fence.proxy.async.shared::cta;" ::: "memory");
            if (warp == 4 && elect1()) {
                asm volatile("tcgen05.fence::after_thread_sync;" ::: "memory");
                const uint32_t kvn = sb + ASM_KV + (uint32_t)((j + 1) & 1) * ASM_KV_STAGE;
                const uint32_t dtm = tmem + ((j + 1) & 1) * 64;
                uint64_t aoff[3] = { 0, 0, 32768 };
                uint64_t boff[3] = { 0, 16384, 0 };
#pragma unroll
                for (int p = 0; p < 3; p++)
#pragma unroll
                    for (int k = 0; k < 8; k++) {
                        int d = k >> 2, kk = k & 3;
                        uint64_t ad = mk_desc128(sb + ASM_QH + (uint32_t)aoff[p] + d * 16384) + kk * 2;
                        uint64_t bd = mk_desc128(kvn + (uint32_t)boff[p] + d * 8192) + kk * 2;
                        TCMMA(dtm, ad, bd, AIDESC, (p == 0 && k == 0) ? 0u : 1u);
                    }
                asm volatile(
                    "tcgen05.commit.cta_group::1.mbarrier::arrive::one.shared::cluster.b64 [%0];"
                    :: "r"(sb + 8 + 8 * ((j + 1) & 1)) : "memory");
            }
        }

        // 4. pass 2 (warps 0-3): re-read S in 16-col chunks, exp+pack+STS
        if (warp < 4) {
            float sum = 0.0f;
#pragma unroll
            for (int hq = 0; hq < 4; hq++) {
                uint32_t s16[16];
                TCLD_X16(s16, tmem + scur * 64 + hq * 16);
                asm volatile("tcgen05.wait::ld.sync.aligned;" ::: "memory");
                float p[16];
#pragma unroll
                for (int c = 0; c < 16; c++) {
                    float v = __uint_as_float(s16[c]) * SCALE_F;
                    if (needmask && (k0 + hq * 16 + c > grow)) v = -CUDART_INF_F;
                    p[c] = __expf(v - m_new);
                    sum += p[c];
                }
                uint32_t hh[8], ll[8];
#pragma unroll
                for (int q = 0; q < 8; q++)
                    split_pack2(p[2 * q], p[2 * q + 1], hh[q], ll[q]);
                STS128(sb + ASM_PH + APSW(qrow, 2 * hq),     hh[0], hh[1], hh[2], hh[3]);
                STS128(sb + ASM_PH + APSW(qrow, 2 * hq + 1), hh[4], hh[5], hh[6], hh[7]);
                STS128(sb + ASM_PL + APSW(qrow, 2 * hq),     ll[0], ll[1], ll[2], ll[3]);
                STS128(sb + ASM_PL + APSW(qrow, 2 * hq + 1), ll[4], ll[5], ll[6], ll[7]);
            }
            l_run = l_run * alpha + sum;
            m_prev = m_new;
            alphaArr[qrow] = alpha;
            asm volatile("tcgen05.fence::before_thread_sync;" ::: "memory");
        }
        __syncthreads();

        // 5. PV (all 8 warps): rescale + P·V
        {
            float a0 = alphaArr[arow + (lane >> 2)];
            float a1 = alphaArr[arow + 8 + (lane >> 2)];
#pragma unroll
            for (int nt = 0; nt < 16; nt++) {
                oacc[nt][0] *= a0; oacc[nt][1] *= a0;
                oacc[nt][2] *= a1; oacc[nt][3] *= a1;
            }
            const uint32_t vbh = kvs + 32768;
            const uint32_t vbl = kvs + 49152;
#pragma unroll
            for (int s2 = 0; s2 < 4; s2++) {
                uint32_t pah[4], pal[4];
                LDSM4(pah, sb + ASM_PH + APSW(arow + (lane & 15), 2 * s2 + (lane >> 4)));
                LDSM4(pal, sb + ASM_PL + APSW(arow + (lane & 15), 2 * s2 + (lane >> 4)));
#pragma unroll
                for (int np = 0; np < 8; np++) {
                    uint32_t vh4[4], vl4[4];
                    int vrow = s2 * 16 + (lane & 7) + (((lane >> 3) & 1) << 3);
                    int vch  = 2 * np + (lane >> 4);
                    LDSM4T(vh4, vbh + SOFF2(vrow, vch));
                    LDSM4T(vl4, vbl + SOFF2(vrow, vch));
                    MMA_BF16(oacc[2 * np],     pah, vh4 + 0);
                    MMA_BF16(oacc[2 * np],     pah, vl4 + 0);
                    MMA_BF16(oacc[2 * np],     pal, vh4 + 0);
                    MMA_BF16(oacc[2 * np + 1], pah, vh4 + 2);
                    MMA_BF16(oacc[2 * np + 1], pah, vl4 + 2);
                    MMA_BF16(oacc[2 * np + 1], pal, vh4 + 2);
                }
            }
        }

        // 6. prefetch KV_{j+2} into this stage (after all PV reads done)
        if (j + 2 <= jmax) {
            __syncthreads();
            atc_load_kv(kvs, kh_g, kl_g, vh_g, vl_g, (j + 2) * 64, tid);
        }
    }

    // epilogue: invl via smem, scale + split-store
    __syncthreads();
    if (warp < 4) alphaArr[qrow] = 1.0f / l_run;
    __syncthreads();
    {
        float inv0 = alphaArr[arow + (lane >> 2)];
        float inv1 = alphaArr[arow + 8 + (lane >> 2)];
        __nv_bfloat16* ch = Chi + rowbase;
        __nv_bfloat16* cl = Clo + rowbase;
#pragma unroll
        for (int nt = 0; nt < 16; nt++) {
            int c0 = nt * 8 + (lane & 3) * 2;
            size_t i0 = (size_t)(q0 + arow + (lane >> 2)) * Ddim + c0;
            size_t i1 = i0 + (size_t)8 * Ddim;
            store_split2(&ch[i0], &cl[i0], oacc[nt][0] * inv0, oacc[nt][1] * inv0);
            store_split2(&ch[i1], &cl[i1], oacc[nt][2] * inv1, oacc[nt][3] * inv1);
        }
    }
    __syncthreads();
    if (warp == 0) {
        asm volatile("tcgen05.relinquish_alloc_permit.cta_group::1.sync.aligned;");
        asm volatile("tcgen05.dealloc.cta_group::1.sync.aligned.b32 %0, %1;"
                     :: "r"(tmem), "r"(128u));
    }

#else
    // =====================================================================
    // mma.sync fallback (validated R5-R9)
    // =====================================================================
    const int arow = warp * 16;
    {
        const __nv_bfloat16* gq[2] = { qh_g, ql_g };
#pragma unroll
        for (int a2 = 0; a2 < 2; a2++)
#pragma unroll
            for (int i = 0; i < 8; i++) {
                int u = i * 256 + tid;
                int r = u >> 4, c = u & 15;
                cp16(sb + a2 * 32768 + SOFF2(r, c), gq[a2] + (size_t)r * Ddim + c * 8);
            }
        const __nv_bfloat16* gp0[4] = { kh_g, kl_g, vh_g, vl_g };
#pragma unroll
        for (int a2 = 0; a2 < 4; a2++)
#pragma unroll
            for (int i = 0; i < 4; i++) {
                int u = i * 256 + tid;
                int r = u >> 4, c = u & 15;
                cp16(sb + 65536 + a2 * 16384 + SOFF2(r, c), gp0[a2] + (size_t)r * Ddim + c * 8);
            }
        asm volatile("cp.async.commit_group;" ::: "memory");
#pragma unroll
        for (int a2 = 0; a2 < 4; a2++)
#pragma unroll
            for (int i = 0; i < 4; i++) {
                int u = i * 256 + tid;
                int r = u >> 4, c = u & 15;
                cp16(sb + 65536 + 65536 + a2 * 16384 + SOFF2(r, c),
                     gp0[a2] + (size_t)(64 + r) * Ddim + c * 8);
            }
        asm volatile("cp.async.commit_group;" ::: "memory");
    }
    asm volatile("cp.async.wait_group 1;" ::: "memory");
    __syncthreads();

    uint32_t qfh[8][4];
#pragma unroll
    for (int s = 0; s < 8; s++)
        LDSM4(qfh[s], sb + SOFF2(arow + (lane & 15), 2 * s + (lane >> 4)));

    float oacc[16][4];
#pragma unroll
    for (int nt = 0; nt < 16; nt++)
#pragma unroll
        for (int e = 0; e < 4; e++) oacc[nt][e] = 0.0f;
    float m0 = -CUDART_INF_F, m1 = -CUDART_INF_F, l0 = 0.0f, l1 = 0.0f;
    const int row0 = q0 + arow + (lane >> 2);
    const int row1 = row0 + 8;

    for (int j = 0; j <= jmax; j++) {
        if (j > 0) {
            if (j < jmax) { asm volatile("cp.async.wait_group 1;" ::: "memory"); }
            else          { asm volatile("cp.async.wait_group 0;" ::: "memory"); }
            __syncthreads();
        }
        const uint32_t kbase = sb + 65536 + (uint32_t)(j & 1) * 65536;
        const int k0 = j * 64;

        float sacc[8][4];
#pragma unroll
        for (int nt = 0; nt < 8; nt++)
#pragma unroll
            for (int e = 0; e < 4; e++) sacc[nt][e] = 0.0f;

#pragma unroll
        for (int s = 0; s < 8; s++) {
            uint32_t ql4[4];
            LDSM4(ql4, sb + 32768 + SOFF2(arow + (lane & 15), 2 * s + (lane >> 4)));
#pragma unroll
            for (int np = 0; np < 4; np++) {
                uint32_t kh4[4], kl4[4];
                int krow = np * 16 + (lane & 7) + ((lane >> 4) << 3);
                int kch  = 2 * s + ((lane >> 3) & 1);
                LDSM4(kh4, kbase + SOFF2(krow, kch));
                LDSM4(kl4, kbase + 16384 + SOFF2(krow, kch));
                MMA_BF16(sacc[2 * np],     qfh[s], kh4 + 0);
                MMA_BF16(sacc[2 * np],     qfh[s], kl4 + 0);
                MMA_BF16(sacc[2 * np],     ql4,    kh4 + 0);
                MMA_BF16(sacc[2 * np + 1], qfh[s], kh4 + 2);
                MMA_BF16(sacc[2 * np + 1], qfh[s], kl4 + 2);
                MMA_BF16(sacc[2 * np + 1], ql4,    kh4 + 2);
            }
        }

        const bool diag = (k0 + 63 > q0 + arow);
        float mx0 = -CUDART_INF_F, mx1 = -CUDART_INF_F;
#pragma unroll
        for (int nt = 0; nt < 8; nt++) {
            float v0 = sacc[nt][0] * SCALE_F;
            float v1 = sacc[nt][1] * SCALE_F;
            float v2 = sacc[nt][2] * SCALE_F;
            float v3 = sacc[nt][3] * SCALE_F;
            if (diag) {
                int colb = k0 + nt * 8 + ((lane & 3) << 1);
                if (colb     > row0) v0 = -CUDART_INF_F;
                if (colb + 1 > row0) v1 = -CUDART_INF_F;
                if (colb     > row1) v2 = -CUDART_INF_F;
                if (colb + 1 > row1) v3 = -CUDART_INF_F;
            }
            sacc[nt][0] = v0; sacc[nt][1] = v1; sacc[nt][2] = v2; sacc[nt][3] = v3;
            mx0 = fmaxf(mx0, fmaxf(v0, v1));
            mx1 = fmaxf(mx1, fmaxf(v2, v3));
        }
        mx0 = fmaxf(mx0, __shfl_xor_sync(0xffffffffu, mx0, 1));
        mx0 = fmaxf(mx0, __shfl_xor_sync(0xffffffffu, mx0, 2));
        mx1 = fmaxf(mx1, __shfl_xor_sync(0xffffffffu, mx1, 1));
        mx1 = fmaxf(mx1, __shfl_xor_sync(0xffffffffu, mx1, 2));

        float mn0 = fmaxf(m0, mx0), mn1 = fmaxf(m1, mx1);
        float a0 = __expf(m0 - mn0), a1 = __expf(m1 - mn1);
        float s0 = 0.0f, s1 = 0.0f;
#pragma unroll
        for (int nt = 0; nt < 8; nt++) {
            float p0 = __expf(sacc[nt][0] - mn0);
            float p1 = __expf(sacc[nt][1] - mn0);
            float p2 = __expf(sacc[nt][2] - mn1);
            float p3 = __expf(sacc[nt][3] - mn1);
            sacc[nt][0] = p0; sacc[nt][1] = p1; sacc[nt][2] = p2; sacc[nt][3] = p3;
            s0 += p0 + p1;
            s1 += p2 + p3;
        }
        s0 += __shfl_xor_sync(0xffffffffu, s0, 1);
        s0 += __shfl_xor_sync(0xffffffffu, s0, 2);
        s1 += __shfl_xor_sync(0xffffffffu, s1, 1);
        s1 += __shfl_xor_sync(0xffffffffu, s1, 2);
        l0 = l0 * a0 + s0;
        l1 = l1 * a1 + s1;
        m0 = mn0; m1 = mn1;
#pragma unroll
        for (int nt = 0; nt < 16; nt++) {
            oacc[nt][0] *= a0; oacc[nt][1] *= a0;
            oacc[nt][2] *= a1; oacc[nt][3] *= a1;
        }

        uint32_t pah[4][4], pal[4][4];
#pragma unroll
        for (int s2 = 0; s2 < 4; s2++) {
            split_pack2(sacc[2 * s2][0],     sacc[2 * s2][1],     pah[s2][0], pal[s2][0]);
            split_pack2(sacc[2 * s2][2],     sacc[2 * s2][3],     pah[s2][1], pal[s2][1]);
            split_pack2(sacc[2 * s2 + 1][0], sacc[2 * s2 + 1][1], pah[s2][2], pal[s2][2]);
            split_pack2(sacc[2 * s2 + 1][2], sacc[2 * s2 + 1][3], pah[s2][3], pal[s2][3]);
        }

#pragma unroll
        for (int s2 = 0; s2 < 4; s2++) {
#pragma unroll
            for (int np = 0; np < 8; np++) {
                uint32_t vh4[4], vl4[4];
                int vrow = s2 * 16 + (lane & 7) + (((lane >> 3) & 1) << 3);
                int vch  = 2 * np + (lane >> 4);
                LDSM4T(vh4, kbase + 32768 + SOFF2(vrow, vch));
                LDSM4T(vl4, kbase + 49152 + SOFF2(vrow, vch));
                MMA_BF16(oacc[2 * np],     pah[s2], vh4 + 0);
                MMA_BF16(oacc[2 * np],     pah[s2], vl4 + 0);
                MMA_BF16(oacc[2 * np],     pal[s2], vh4 + 0);
                MMA_BF16(oacc[2 * np + 1], pah[s2], vh4 + 2);
                MMA_BF16(oacc[2 * np + 1], pah[s2], vl4 + 2);
                MMA_BF16(oacc[2 * np + 1], pal[s2], vh4 + 2);
            }
        }

        __syncthreads();
        if (j + 2 <= jmax) {
            size_t off = (size_t)(j + 2) * 64 * Ddim;
            const __nv_bfloat16* gp2[4] = { kh_g + off, kl_g + off, vh_g + off, vl_g + off };
#pragma unroll
            for (int a2 = 0; a2 < 4; a2++)
#pragma unroll
                for (int i = 0; i < 4; i++) {
                    int u = i * 256 + tid;
                    int r = u >> 4, c = u & 15;
                    cp16(sb + 65536 + (uint32_t)(j & 1) * 65536 + a2 * 16384 + SOFF2(r, c),
                         gp2[a2] + (size_t)r * Ddim + c * 8);
                }
            asm volatile("cp.async.commit_group;" ::: "memory");
        }
    }

    float inv0 = 1.0f / l0, inv1 = 1.0f / l1;
    __nv_bfloat16* ch = Chi + rowbase;
    __nv_bfloat16* cl = Clo + rowbase;
#pragma unroll
    for (int nt = 0; nt < 16; nt++) {
        int c0 = nt * 8 + (lane & 3) * 2;
        size_t i0 = (size_t)(q0 + arow + (lane >> 2)) * Ddim + c0;
        size_t i1 = i0 + (size_t)8 * Ddim;
        store_split2(&ch[i0], &cl[i0], oacc[nt][0] * inv0, oacc[nt][1] * inv0);
        store_split2(&ch[i1], &cl[i1], oacc[nt][2] * inv1, oacc[nt][3] * inv1);
    }
#endif  // GEMM_TCGEN05
}

// ---------------------------------------------------------------------------
extern "C" void kernel_launch(void* const* d_in, const int* in_sizes, int n_in,
                              void* d_out, int out_size)
{
    const float* x  = (const float*)d_in[0];
    const float* Wq = (const float*)d_in[1];
    const float* Wk = (const float*)d_in[2];
    const float* Wv = (const float*)d_in[3];
    const float* Wo = (const float*)d_in[4];
    float* out = (float*)d_out;

    __nv_bfloat16 *xhi, *xlo, *whi, *wlo, *qkvhi, *qkvlo, *chi, *clo;
    cudaGetSymbolAddress((void**)&xhi, g_xhi);
    cudaGetSymbolAddress((void**)&xlo, g_xlo);
    cudaGetSymbolAddress((void**)&whi, g_whi);
    cudaGetSymbolAddress((void**)&wlo, g_wlo);
    cudaGetSymbolAddress((void**)&qkvhi, g_qkvhi);
    cudaGetSymbolAddress((void**)&qkvlo, g_qkvlo);
    cudaGetSymbolAddress((void**)&chi, g_chi);
    cudaGetSymbolAddress((void**)&clo, g_clo);

    const size_t DD = (size_t)Ddim * Ddim;
    const size_t MD = (size_t)MROWS * Ddim;

    // one fused split launch (8 floats/thread)
    const int total8 = XN8 + 4 * WN8;
    split_all<<<total8 / 256, 256>>>(x, Wq, Wk, Wv, Wo, xhi, xlo, whi, wlo);

    cudaFuncSetAttribute(gemm_any, cudaFuncAttributeMaxDynamicSharedMemorySize,
                         GSMEM_UNIFIED);

    // fused Q/K/V projections -> bf16 hi/lo split outputs (256x256 tiles)
    dim3 gqkv(Ddim / 256, MROWS / 256, 3);   // (8, 16, 3)
    gemm_any<<<gqkv, 256, GSMEM_UNIFIED>>>(xhi, xlo, whi, wlo, DD,
                                           qkvhi, qkvlo, MD, nullptr,
                                           MROWS, Ddim, Ddim);

    // attention -> ctx bf16 hi/lo split
    cudaFuncSetAttribute(attn_any, cudaFuncAttributeMaxDynamicSharedMemorySize,
                         ASMEM_TOTAL);
    dim3 ga(Sdim / 128, Bdim * Hdim);   // (8, 64)
    attn_any<<<ga, 256, ASMEM_TOTAL>>>(qkvhi, qkvlo, qkvhi + MD, qkvlo + MD,
                                       qkvhi + 2 * MD, qkvlo + 2 * MD, chi, clo);

    // output projection -> fp32 out
    dim3 go(Ddim / 256, MROWS / 256, 1);   // (8, 16)
    gemm_any<<<go, 256, GSMEM_UNIFIED>>>(chi, clo, whi + 3 * DD, wlo + 3 * DD, 0,
                                         nullptr, nullptr, 0, out,
                                         MROWS, Ddim, Ddim);
}

// round 14
// speedup vs baseline: 1.0385x; 1.0385x over previous
#include <cuda_runtime.h>
#include <cuda_bf16.h>
#include <math_constants.h>
#include <cstdint>

// Problem constants
#define Bdim 4
#define Sdim 1024
#define Ddim 2048
#define Hdim 16
#define DHdim 128
#define MROWS (Bdim * Sdim)   // 4096

static const float SCALE_F = 11.313708498984761f;  // sqrt(128)

// tcgen05 is arch-specific ("a") — only compile it on the sm_103a pass.
#if defined(__CUDA_ARCH_FEAT_SM103_ALL) || \
    (defined(__CUDA_ARCH_SPECIFIC__) && defined(__CUDA_ARCH__) && (__CUDA_ARCH__ == 1030))
#define GEMM_TCGEN05 1
#endif

// ---------------------------------------------------------------------------
// Scratch (allocation-free rule: __device__ globals)
// ---------------------------------------------------------------------------
__device__ __align__(256) __nv_bfloat16 g_xhi[MROWS * Ddim];
__device__ __align__(256) __nv_bfloat16 g_xlo[MROWS * Ddim];
__device__ __align__(256) __nv_bfloat16 g_whi[4][Ddim * Ddim];
__device__ __align__(256) __nv_bfloat16 g_wlo[4][Ddim * Ddim];
__device__ __align__(256) __nv_bfloat16 g_qkvhi[3][MROWS * Ddim];
__device__ __align__(256) __nv_bfloat16 g_qkvlo[3][MROWS * Ddim];
__device__ __align__(256) __nv_bfloat16 g_chi[MROWS * Ddim];
__device__ __align__(256) __nv_bfloat16 g_clo[MROWS * Ddim];

// ---------------------------------------------------------------------------
// Helpers
// ---------------------------------------------------------------------------
__device__ __forceinline__ uint32_t smem_u32(const void* p) {
    uint32_t a;
    asm("{ .reg .u64 t; cvta.to.shared.u64 t, %1; cvt.u32.u64 %0, t; }"
        : "=r"(a) : "l"(p));
    return a;
}

__device__ __forceinline__ void cp16(uint32_t dst, const void* src) {
    asm volatile("cp.async.cg.shared.global [%0], [%1], 16;"
                 :: "r"(dst), "l"(src));
}

#define LDSM4(r, addr) \
    asm volatile("ldmatrix.sync.aligned.m8n8.x4.shared.b16 {%0,%1,%2,%3}, [%4];" \
        : "=r"((r)[0]), "=r"((r)[1]), "=r"((r)[2]), "=r"((r)[3]) : "r"(addr))

#define LDSM4T(r, addr) \
    asm volatile("ldmatrix.sync.aligned.m8n8.x4.trans.shared.b16 {%0,%1,%2,%3}, [%4];" \
        : "=r"((r)[0]), "=r"((r)[1]), "=r"((r)[2]), "=r"((r)[3]) : "r"(addr))

#define MMA_BF16(d, a, b) \
    asm volatile("mma.sync.aligned.m16n8k16.row.col.f32.bf16.bf16.f32 " \
        "{%0,%1,%2,%3}, {%4,%5,%6,%7}, {%8,%9}, {%0,%1,%2,%3};" \
        : "+f"((d)[0]), "+f"((d)[1]), "+f"((d)[2]), "+f"((d)[3]) \
        : "r"((a)[0]), "r"((a)[1]), "r"((a)[2]), "r"((a)[3]), \
          "r"((b)[0]), "r"((b)[1]))

#define STS128(addr, r0, r1, r2, r3) \
    asm volatile("st.shared.v4.b32 [%0], {%1,%2,%3,%4};" \
        :: "r"(addr), "r"(r0), "r"(r1), "r"(r2), "r"(r3) : "memory")

// split f32 pair -> packed bf16x2 hi + bf16x2 lo
__device__ __forceinline__ void split_pack2(float x, float y,
                                            uint32_t& hi, uint32_t& lo) {
    __nv_bfloat16 bx = __float2bfloat16_rn(x), by = __float2bfloat16_rn(y);
    __nv_bfloat162 h; h.x = bx; h.y = by;
    hi = *(uint32_t*)&h;
    __nv_bfloat162 l;
    l.x = __float2bfloat16_rn(x - __bfloat162float(bx));
    l.y = __float2bfloat16_rn(y - __bfloat162float(by));
    lo = *(uint32_t*)&l;
}

__device__ __forceinline__ void store_split2(__nv_bfloat16* ph, __nv_bfloat16* pl,
                                             float x, float y) {
    uint32_t hi, lo;
    split_pack2(x, y, hi, lo);
    *(uint32_t*)ph = hi;
    *(uint32_t*)pl = lo;
}

// ---------------------------------------------------------------------------
// Fused split: x + all 4 weights in ONE launch; 8 floats per thread.
// ---------------------------------------------------------------------------
#define XN8 (MROWS * Ddim / 8)      // 2^20
#define WN8 (Ddim * Ddim / 8)       // 2^19

__global__ __launch_bounds__(256) void split_all(
    const float* __restrict__ x,
    const float* __restrict__ W0, const float* __restrict__ W1,
    const float* __restrict__ W2, const float* __restrict__ W3,
    __nv_bfloat16* __restrict__ xhi, __nv_bfloat16* __restrict__ xlo,
    __nv_bfloat16* __restrict__ whi, __nv_bfloat16* __restrict__ wlo)
{
    int i = blockIdx.x * 256 + threadIdx.x;   // unit = 8 floats
    const float* in;
    __nv_bfloat16 *hi, *lo;
    int off;
    if (i < XN8) {
        in = x; hi = xhi; lo = xlo; off = i;
    } else {
        int t = i - XN8;
        int r = t >> 19;            // / WN8
        off = t & (WN8 - 1);
        in = (r == 0) ? W0 : (r == 1) ? W1 : (r == 2) ? W2 : W3;
        hi = whi + (size_t)r * (Ddim * Ddim);
        lo = wlo + (size_t)r * (Ddim * Ddim);
    }
    const float4* p4 = (const float4*)in + 2 * (size_t)off;
    float4 v0 = p4[0], v1 = p4[1];
    uint32_t h[4], l[4];
    split_pack2(v0.x, v0.y, h[0], l[0]);
    split_pack2(v0.z, v0.w, h[1], l[1]);
    split_pack2(v1.x, v1.y, h[2], l[2]);
    split_pack2(v1.z, v1.w, h[3], l[3]);
    ((uint4*)hi)[off] = make_uint4(h[0], h[1], h[2], h[3]);
    ((uint4*)lo)[off] = make_uint4(l[0], l[1], l[2], l[3]);
}

// ---------------------------------------------------------------------------
// Unified bf16x2-split GEMM (validated R9-R12): 256x256 tile tcgen05 path +
// mma.sync fallback.  C ~= Ahi*Bhi + Ahi*Blo + Alo*Bhi.
// ---------------------------------------------------------------------------
#define TSTAGES 3
#define TKC 32
#define TOP_BUF 16384                          // 256 rows x 64B per operand buf
#define TSTAGE_BYTES (4 * TOP_BUF)             // 64KB
#define TCTRL 1024
#define GSMEM_UNIFIED (TCTRL + TSTAGES * TSTAGE_BYTES)   // 197632
#define TIDESC 0x8400490u
#define TMEM_COLS_ALLOC 512u

#define MSTAGES 4
#define MKC 32
#define MBUF 8192
#define MSTAGE_BYTES (4 * MBUF)

__device__ __forceinline__ uint32_t soff(int r, int c) {
    return (uint32_t)(r * 64 + ((c ^ ((r >> 1) & 3)) << 4));
}

__device__ __forceinline__ void ld_chunk(uint32_t stg,
    const __nv_bfloat16* a1, const __nv_bfloat16* a2,
    const __nv_bfloat16* b1, const __nv_bfloat16* b2, int K, int tid)
{
    const __nv_bfloat16* gp[4] = { a1, a2, b1, b2 };
#pragma unroll
    for (int b = 0; b < 4; b++) {
        uint32_t base = stg + b * MBUF;
#pragma unroll
        for (int i = 0; i < 2; i++) {
            int u = i * 256 + tid;
            int r = u >> 2, c = u & 3;
            cp16(base + soff(r, c), gp[b] + (size_t)r * K + c * 8);
        }
    }
    asm volatile("cp.async.commit_group;" ::: "memory");
}

#ifdef GEMM_TCGEN05
#define SW64(x) ((x) ^ (((x) >> 3) & 0x30))
#define SW128(x) ((x) ^ (((x) >> 3) & 0x70))

__device__ __forceinline__ uint64_t mk_desc64(uint32_t addr) {
    return ((uint64_t)4 << 61) | ((uint64_t)1 << 46) | ((uint64_t)32 << 32)
         | ((uint64_t)1 << 16) | ((addr >> 4) & 0x3FFF);
}
__device__ __forceinline__ uint64_t mk_desc128(uint32_t addr) {
    return ((uint64_t)2 << 61) | ((uint64_t)1 << 46) | ((uint64_t)64 << 32)
         | ((uint64_t)1 << 16) | ((addr >> 4) & 0x3FFF);
}

__device__ __forceinline__ uint32_t elect1() {
    uint32_t p;
    asm volatile("{ .reg .pred p; elect.sync _|p, 0xFFFFFFFF; selp.b32 %0, 1, 0, p; }"
                 : "=r"(p));
    return p;
}

__device__ __forceinline__ void mbar_wait(uint32_t addr, int parity) {
    asm volatile(
        "{\n\t"
        ".reg .pred P1;\n\t"
        "WAIT_LOOP_%=:\n\t"
        "mbarrier.try_wait.parity.acquire.cta.shared::cta.b64 P1, [%0], %1, 0x989680;\n\t"
        "@P1 bra.uni WAIT_DONE_%=;\n\t"
        "bra.uni WAIT_LOOP_%=;\n\t"
        "WAIT_DONE_%=:\n\t"
        "}"
        :: "r"(addr), "r"((uint32_t)parity) : "memory");
}

#define TCLD_X32(r, tmem_addr) \
    asm volatile( \
        "tcgen05.ld.sync.aligned.32x32b.x32.b32 " \
        "{%0, %1, %2, %3, %4, %5, %6, %7, " \
        " %8, %9, %10, %11, %12, %13, %14, %15, " \
        " %16, %17, %18, %19, %20, %21, %22, %23, " \
        " %24, %25, %26, %27, %28, %29, %30, %31}, [%32];" \
        : "=r"((r)[0]),  "=r"((r)[1]),  "=r"((r)[2]),  "=r"((r)[3]), \
          "=r"((r)[4]),  "=r"((r)[5]),  "=r"((r)[6]),  "=r"((r)[7]), \
          "=r"((r)[8]),  "=r"((r)[9]),  "=r"((r)[10]), "=r"((r)[11]), \
          "=r"((r)[12]), "=r"((r)[13]), "=r"((r)[14]), "=r"((r)[15]), \
          "=r"((r)[16]), "=r"((r)[17]), "=r"((r)[18]), "=r"((r)[19]), \
          "=r"((r)[20]), "=r"((r)[21]), "=r"((r)[22]), "=r"((r)[23]), \
          "=r"((r)[24]), "=r"((r)[25]), "=r"((r)[26]), "=r"((r)[27]), \
          "=r"((r)[28]), "=r"((r)[29]), "=r"((r)[30]), "=r"((r)[31]) \
        : "r"(tmem_addr))

#define TCMMA(dtm, adesc, bdesc, idesc, en) \
    asm volatile( \
        "{ .reg .pred pp;\n\t" \
        "setp.ne.u32 pp, %4, 0;\n\t" \
        "tcgen05.mma.cta_group::1.kind::f16 [%0], %1, %2, %3, " \
        "{%5, %5, %5, %5}, pp; }\n" \
        :: "r"(dtm), "l"(adesc), "l"(bdesc), "r"(idesc), "r"(en), "r"(0u) \
        : "memory")

__device__ __forceinline__ void ld_chunk_tc(uint32_t stg,
    const __nv_bfloat16* a1, const __nv_bfloat16* a2,
    const __nv_bfloat16* b1, const __nv_bfloat16* b2, int tid)
{
    const __nv_bfloat16* gp[4] = { a1, a2, b1, b2 };
#pragma unroll
    for (int b = 0; b < 4; b++) {
        uint32_t base = stg + b * TOP_BUF;
#pragma unroll
        for (int it = 0; it < 4; it++) {
            int u = it * 256 + tid;
            int r = u >> 2, c16 = u & 3;
            cp16(base + SW64(r * 64 + c16 * 16),
                 gp[b] + (size_t)r * Ddim + c16 * 8);
        }
    }
    asm volatile("cp.async.commit_group;" ::: "memory");
}
#endif  // GEMM_TCGEN05

__global__ __launch_bounds__(256, 1) void gemm_any(
    const __nv_bfloat16* __restrict__ Ahi, const __nv_bfloat16* __restrict__ Alo,
    const __nv_bfloat16* __restrict__ BhiBase, const __nv_bfloat16* __restrict__ BloBase,
    size_t bStride, __nv_bfloat16* ChB, __nv_bfloat16* ClB, size_t cStride,
    float* Cf, int M, int N, int K)
{
    extern __shared__ __align__(1024) char smem[];
    const uint32_t sb = smem_u32(smem);
    const int tid = threadIdx.x, warp = tid >> 5, lane = tid & 31;
    const int z = blockIdx.z;

#ifdef GEMM_TCGEN05
    const int bm = blockIdx.y * 256;
    const int bn = blockIdx.x * 256;
    const __nv_bfloat16* Abh = Ahi + (size_t)bm * K;
    const __nv_bfloat16* Abl = Alo + (size_t)bm * K;
    const __nv_bfloat16* Bbh = BhiBase + (size_t)z * bStride + (size_t)bn * K;
    const __nv_bfloat16* Bbl = BloBase + (size_t)z * bStride + (size_t)bn * K;
    const int nchunk = K / TKC;   // 64

    if (warp == 0)
        asm volatile("tcgen05.alloc.cta_group::1.sync.aligned.shared::cta.b32 [%0], %1;"
                     :: "r"(sb), "r"(TMEM_COLS_ALLOC) : "memory");
    if (tid == 0) {
#pragma unroll
        for (int s = 0; s < TSTAGES; s++)
            asm volatile("mbarrier.init.shared.b64 [%0], 1;"
                         :: "r"(sb + 8 + 8 * s) : "memory");
    }
    __syncthreads();
    uint32_t tmem;
    asm volatile("ld.shared.b32 %0, [%1];" : "=r"(tmem) : "r"(sb));

    ld_chunk_tc(sb + TCTRL, Abh, Abl, Bbh, Bbl, tid);
    ld_chunk_tc(sb + TCTRL + TSTAGE_BYTES, Abh + TKC, Abl + TKC,
                Bbh + TKC, Bbl + TKC, tid);

    int ph[TSTAGES] = { 0, 0, 0 };

    for (int i = 0; i < nchunk; i++) {
        const int s = i % TSTAGES;
        if (i < nchunk - 1) { asm volatile("cp.async.wait_group 1;" ::: "memory"); }
        else                { asm volatile("cp.async.wait_group 0;" ::: "memory"); }
        __syncthreads();
        asm volatile("fence.proxy.async.shared::cta;" ::: "memory");

        if (warp == 0 && elect1()) {
            const uint32_t stg = sb + TCTRL + s * TSTAGE_BYTES;
            uint64_t dAh = mk_desc64(stg);
            uint64_t dAl = mk_desc64(stg + TOP_BUF);
            uint64_t dBh = mk_desc64(stg + 2 * TOP_BUF);
            uint64_t dBl = mk_desc64(stg + 3 * TOP_BUF);
            uint64_t ad[3] = { dAh, dAh, dAl };
            uint64_t bd[3] = { dBh, dBl, dBh };
#pragma unroll
            for (int p = 0; p < 3; p++)
#pragma unroll
                for (int k = 0; k < 2; k++) {
                    uint32_t en = (i == 0 && p == 0 && k == 0) ? 0u : 1u;
#pragma unroll
                    for (int mt = 0; mt < 2; mt++)
                        TCMMA(tmem + mt * 256, ad[p] + k * 2 + mt * 512,
                              bd[p] + k * 2, TIDESC, en);
                }
            asm volatile(
                "tcgen05.commit.cta_group::1.mbarrier::arrive::one.shared::cluster.b64 [%0];"
                :: "r"(sb + 8 + 8 * s) : "memory");
        }

        const int j = i + 2;
        if (j < nchunk) {
            const int sj = j % TSTAGES;
            if (i >= 1) {
                mbar_wait(sb + 8 + 8 * sj, ph[sj]);
                ph[sj] ^= 1;
            }
            ld_chunk_tc(sb + TCTRL + sj * TSTAGE_BYTES,
                        Abh + (size_t)j * TKC, Abl + (size_t)j * TKC,
                        Bbh + (size_t)j * TKC, Bbl + (size_t)j * TKC, tid);
        }
    }

    const int sf = (nchunk - 1) % TSTAGES;
    mbar_wait(sb + 8 + 8 * sf, ph[sf]);
    asm volatile("tcgen05.fence::after_thread_sync;" ::: "memory");
    __syncthreads();

    {
        const uint32_t acc = tmem + (uint32_t)(warp >> 2) * 256;
        const int mrow_base = bm + (warp >> 2) * 128 + (warp & 3) * 32;
        float* tr = (float*)(smem + TCTRL) + warp * (32 * 33);
#pragma unroll
        for (int cb = 0; cb < 8; cb++) {
            uint32_t dreg[32];
            TCLD_X32(dreg, acc + cb * 32);
            asm volatile("tcgen05.wait::ld.sync.aligned;" ::: "memory");
#pragma unroll
            for (int c = 0; c < 32; c++)
                tr[lane * 33 + c] = __uint_as_float(dreg[c]);
            __syncwarp();
#pragma unroll
            for (int t = 0; t < 8; t++) {
                int idx = t * 32 + lane;
                int r = idx >> 3;
                int c4 = (idx & 7) * 4;
                int grow = mrow_base + r;
                int gcol = bn + cb * 32 + c4;
                float v0 = tr[r * 33 + c4],     v1 = tr[r * 33 + c4 + 1];
                float v2 = tr[r * 33 + c4 + 2], v3 = tr[r * 33 + c4 + 3];
                if (Cf) {
                    *(float4*)&Cf[(size_t)grow * N + gcol] =
                        make_float4(v0, v1, v2, v3);
                } else {
                    __nv_bfloat16* Ch = ChB + (size_t)z * cStride;
                    __nv_bfloat16* Cl = ClB + (size_t)z * cStride;
                    store_split2(&Ch[(size_t)grow * N + gcol],
                                 &Cl[(size_t)grow * N + gcol], v0, v1);
                    store_split2(&Ch[(size_t)grow * N + gcol + 2],
                                 &Cl[(size_t)grow * N + gcol + 2], v2, v3);
                }
            }
            __syncwarp();
        }
    }

    asm volatile("tcgen05.fence::before_thread_sync;" ::: "memory");
    __syncthreads();
    if (warp == 0) {
        asm volatile("tcgen05.relinquish_alloc_permit.cta_group::1.sync.aligned;");
        asm volatile("tcgen05.dealloc.cta_group::1.sync.aligned.b32 %0, %1;"
                     :: "r"(tmem), "r"(TMEM_COLS_ALLOC));
    }

#else
    for (int mm = 0; mm < 2; mm++)
    for (int nn = 0; nn < 2; nn++) {
        const int bmq = blockIdx.y * 256 + mm * 128;
        const int bn = blockIdx.x * 256 + nn * 128;
        const __nv_bfloat16* Abh = Ahi + (size_t)bmq * K;
        const __nv_bfloat16* Abl = Alo + (size_t)bmq * K;
        const __nv_bfloat16* Bbh = BhiBase + (size_t)z * bStride + (size_t)bn * K;
        const __nv_bfloat16* Bbl = BloBase + (size_t)z * bStride + (size_t)bn * K;

        float acc[4][4][4];
#pragma unroll
        for (int mt = 0; mt < 4; mt++)
#pragma unroll
            for (int nt = 0; nt < 4; nt++)
#pragma unroll
                for (int q = 0; q < 4; q++) acc[mt][nt][q] = 0.0f;

        const int nchunk = K / MKC;
        __syncthreads();
#pragma unroll
        for (int s = 0; s < MSTAGES - 1; s++)
            ld_chunk(sb + s * MSTAGE_BYTES, Abh + s * MKC, Abl + s * MKC,
                     Bbh + s * MKC, Bbl + s * MKC, K, tid);

        const int arow_base = (warp >> 2) * 64;
        const int brow_base = (warp & 3) * 32;

        for (int i = 0; i < nchunk; i++) {
            asm volatile("cp.async.wait_group %0;" :: "n"(MSTAGES - 2) : "memory");
            __syncthreads();
            const int j = i + MSTAGES - 1;
            if (j < nchunk)
                ld_chunk(sb + (j & (MSTAGES - 1)) * MSTAGE_BYTES,
                         Abh + j * MKC, Abl + j * MKC, Bbh + j * MKC, Bbl + j * MKC,
                         K, tid);
            const uint32_t stg = sb + (i & (MSTAGES - 1)) * MSTAGE_BYTES;
#pragma unroll
            for (int s = 0; s < 2; s++) {
                uint32_t ah[4][4], al[4][4], bh[2][4], bl[2][4];
#pragma unroll
                for (int mt = 0; mt < 4; mt++) {
                    int row = arow_base + mt * 16 + (lane & 15);
                    int ch  = s * 2 + (lane >> 4);
                    uint32_t ad = stg + soff(row, ch);
                    LDSM4(ah[mt], ad);
                    LDSM4(al[mt], ad + MBUF);
                }
#pragma unroll
                for (int nt2 = 0; nt2 < 2; nt2++) {
                    int row = brow_base + nt2 * 16 + (lane & 7) + ((lane >> 4) << 3);
                    int ch  = s * 2 + ((lane >> 3) & 1);
                    uint32_t bd = stg + 2 * MBUF + soff(row, ch);
                    LDSM4(bh[nt2], bd);
                    LDSM4(bl[nt2], bd + MBUF);
                }
#pragma unroll
                for (int mt = 0; mt < 4; mt++)
#pragma unroll
                    for (int nt = 0; nt < 4; nt++) {
                        uint32_t* bH = &bh[nt >> 1][(nt & 1) * 2];
                        uint32_t* bL = &bl[nt >> 1][(nt & 1) * 2];
                        MMA_BF16(acc[mt][nt], ah[mt], bH);
                        MMA_BF16(acc[mt][nt], ah[mt], bL);
                        MMA_BF16(acc[mt][nt], al[mt], bH);
                    }
            }
        }

        const int crow0 = bmq + arow_base;
        const int ccol0 = bn + brow_base;
        if (Cf) {
#pragma unroll
            for (int mt = 0; mt < 4; mt++)
#pragma unroll
                for (int nt = 0; nt < 4; nt++) {
                    int r0 = crow0 + mt * 16 + (lane >> 2);
                    int c0 = ccol0 + nt * 8 + (lane & 3) * 2;
                    *(float2*)&Cf[(size_t)r0 * N + c0] =
                        make_float2(acc[mt][nt][0], acc[mt][nt][1]);
                    *(float2*)&Cf[(size_t)(r0 + 8) * N + c0] =
                        make_float2(acc[mt][nt][2], acc[mt][nt][3]);
                }
        } else {
            __nv_bfloat16* Ch = ChB + (size_t)z * cStride;
            __nv_bfloat16* Cl = ClB + (size_t)z * cStride;
#pragma unroll
            for (int mt = 0; mt < 4; mt++)
#pragma unroll
                for (int nt = 0; nt < 4; nt++) {
                    int r0 = crow0 + mt * 16 + (lane >> 2);
                    int c0 = ccol0 + nt * 8 + (lane & 3) * 2;
                    store_split2(&Ch[(size_t)r0 * N + c0], &Cl[(size_t)r0 * N + c0],
                                 acc[mt][nt][0], acc[mt][nt][1]);
                    store_split2(&Ch[(size_t)(r0 + 8) * N + c0],
                                 &Cl[(size_t)(r0 + 8) * N + c0],
                                 acc[mt][nt][2], acc[mt][nt][3]);
                }
        }
        __syncthreads();
    }
#endif  // GEMM_TCGEN05
}

// ---------------------------------------------------------------------------
// Causal flash attention (R11-validated compute; NEW split K/V load rings
// with early K prefetch to hide cp.async latency).
// sm_103a path: QK^T on tcgen05 (S in TMEM, per-lane row softmax),
// PV on mma.sync with register accumulators, P via smem.
// ---------------------------------------------------------------------------
#define SOFF2(r, c) ((uint32_t)((r) * 256 + ((((c) ^ ((r) & 7))) << 4)))
#define APSW(r, c)  ((uint32_t)((r) * 128 + ((((c) ^ ((r) & 7))) << 4)))

// tc-path smem map
#define ASM_QH 1024
#define ASM_QL (ASM_QH + 32768)     // 33792
#define ASM_PH (ASM_QL + 32768)     // 66560
#define ASM_PL (ASM_PH + 16384)     // 82944
#define ASM_AL (ASM_PL + 16384)     // 99328  (128 floats + pad)
#define ASM_K  100352               // 2 stages x 32KB (Kh 16K | Kl 16K)
#define ASM_K_STAGE 32768
#define ASM_V  (ASM_K + 2 * ASM_K_STAGE)   // 165888; 2 stages x 32KB (Vh|Vl)
#define ASM_V_STAGE 32768
#define ASMEM_TOTAL (ASM_V + 2 * ASM_V_STAGE)   // 231424
#define AIDESC 0x8100490u           // kind::f16, F32, bf16, M=128, N=64

#ifdef GEMM_TCGEN05
__device__ __forceinline__ void atc_load_q(uint32_t sbq,
    const __nv_bfloat16* qh, const __nv_bfloat16* ql, int tid)
{
    const __nv_bfloat16* g[2] = { qh, ql };
#pragma unroll
    for (int hl = 0; hl < 2; hl++)
#pragma unroll
        for (int d = 0; d < 2; d++)
#pragma unroll
            for (int it = 0; it < 4; it++) {
                int u = it * 256 + tid;       // 0..1023
                int r = u >> 3, c = u & 7;
                cp16(sbq + hl * 32768 + d * 16384 + SW128(r * 128 + c * 16),
                     g[hl] + (size_t)r * Ddim + d * 64 + c * 8);
            }
}

// K tile (64 keys): Kh 16K | Kl 16K, each 2 d-halves of 64 rows x 128B SW128.
// NO commit (caller commits).
__device__ __forceinline__ void atc_load_k(uint32_t kbuf,
    const __nv_bfloat16* kh, const __nv_bfloat16* kl, int k0, int tid)
{
    const __nv_bfloat16* gk[2] = { kh, kl };
#pragma unroll
    for (int hl = 0; hl < 2; hl++)
#pragma unroll
        for (int d = 0; d < 2; d++)
#pragma unroll
            for (int it = 0; it < 2; it++) {
                int u = it * 256 + tid;       // 0..511
                int r = u >> 3, c = u & 7;
                cp16(kbuf + hl * 16384 + d * 8192 + SW128(r * 128 + c * 16),
                     gk[hl] + (size_t)(k0 + r) * Ddim + d * 64 + c * 8);
            }
}

// V tile (64 keys x 128 dims): Vh 16K | Vl 16K, SOFF2 layout. NO commit.
__device__ __forceinline__ void atc_load_v(uint32_t vbuf,
    const __nv_bfloat16* vh, const __nv_bfloat16* vl, int k0, int tid)
{
    const __nv_bfloat16* gv[2] = { vh, vl };
#pragma unroll
    for (int hl = 0; hl < 2; hl++)
#pragma unroll
        for (int it = 0; it < 4; it++) {
            int u = it * 256 + tid;           // 0..1023
            int r = u >> 4, c = u & 15;
            cp16(vbuf + hl * 16384 + SOFF2(r, c),
                 gv[hl] + (size_t)(k0 + r) * Ddim + c * 8);
        }
}

#define CPCOMMIT() asm volatile("cp.async.commit_group;" ::: "memory")

// Issue S tile: 3 products, Q (smem SS) x K (smem SS), D = S buf in TMEM.
__device__ __forceinline__ void issue_S_attn(uint32_t sb, uint32_t kstage,
                                             uint32_t dtm)
{
    uint32_t aoff[3] = { 0u, 0u, 32768u };
    uint32_t boff[3] = { 0u, 16384u, 0u };
#pragma unroll
    for (int p = 0; p < 3; p++)
#pragma unroll
        for (int k = 0; k < 8; k++) {
            int d = k >> 2, kk = k & 3;
            uint64_t ad = mk_desc128(sb + ASM_QH + aoff[p] + d * 16384) + kk * 2;
            uint64_t bd = mk_desc128(kstage + boff[p] + d * 8192) + kk * 2;
            TCMMA(dtm, ad, bd, AIDESC, (p == 0 && k == 0) ? 0u : 1u);
        }
}
#endif

__global__ __launch_bounds__(256, 1) void attn_any(
    const __nv_bfloat16* __restrict__ Qhi, const __nv_bfloat16* __restrict__ Qlo,
    const __nv_bfloat16* __restrict__ Khi, const __nv_bfloat16* __restrict__ Klo,
    const __nv_bfloat16* __restrict__ Vhi, const __nv_bfloat16* __restrict__ Vlo,
    __nv_bfloat16* __restrict__ Chi, __nv_bfloat16* __restrict__ Clo)
{
    extern __shared__ __align__(1024) char smem[];
    const uint32_t sb = smem_u32(smem);
    const int tid = threadIdx.x, warp = tid >> 5, lane = tid & 31;
    const int qt = blockIdx.x;
    const int b = blockIdx.y >> 4, h = blockIdx.y & 15;
    const int q0 = qt * 128;
    const int jmax = 2 * qt + 1;

    const size_t rowbase = ((size_t)b * Sdim) * Ddim + (size_t)h * DHdim;
    const __nv_bfloat16* qh_g = Qhi + rowbase + (size_t)q0 * Ddim;
    const __nv_bfloat16* ql_g = Qlo + rowbase + (size_t)q0 * Ddim;
    const __nv_bfloat16* kh_g = Khi + rowbase;
    const __nv_bfloat16* kl_g = Klo + rowbase;
    const __nv_bfloat16* vh_g = Vhi + rowbase;
    const __nv_bfloat16* vl_g = Vlo + rowbase;

#ifdef GEMM_TCGEN05
    // =====================================================================
    // tcgen05 QK^T + mma.sync PV; split K/V rings with early K prefetch
    // =====================================================================
    float* alphaArr = (float*)(smem + ASM_AL);

    if (warp == 0)
        asm volatile("tcgen05.alloc.cta_group::1.sync.aligned.shared::cta.b32 [%0], %1;"
                     :: "r"(sb), "r"(128u) : "memory");
    if (tid == 0) {
        asm volatile("mbarrier.init.shared.b64 [%0], 1;" :: "r"(sb + 8) : "memory");
        asm volatile("mbarrier.init.shared.b64 [%0], 1;" :: "r"(sb + 16) : "memory");
    }
    // prologue groups: G1 = {Q, K0, V0}, G2 = {K1}, G3 = {V1}
    atc_load_q(sb + ASM_QH, qh_g, ql_g, tid);
    atc_load_k(sb + ASM_K, kh_g, kl_g, 0, tid);
    atc_load_v(sb + ASM_V, vh_g, vl_g, 0, tid);
    CPCOMMIT();
    atc_load_k(sb + ASM_K + ASM_K_STAGE, kh_g, kl_g, 64, tid);
    CPCOMMIT();
    atc_load_v(sb + ASM_V + ASM_V_STAGE, vh_g, vl_g, 64, tid);
    CPCOMMIT();
    __syncthreads();
    uint32_t tmem;
    asm volatile("ld.shared.b32 %0, [%1];" : "=r"(tmem) : "r"(sb));

    asm volatile("cp.async.wait_group 2;" ::: "memory");   // G1 done
    __syncthreads();
    asm volatile("fence.proxy.async.shared::cta;" ::: "memory");

    if (warp == 4 && elect1()) {
        issue_S_attn(sb, sb + ASM_K, tmem);   // S_0 -> buf0
        asm volatile(
            "tcgen05.commit.cta_group::1.mbarrier::arrive::one.shared::cluster.b64 [%0];"
            :: "r"(sb + 8) : "memory");
    }

    float oacc[16][4];
#pragma unroll
    for (int nt = 0; nt < 16; nt++)
#pragma unroll
        for (int e = 0; e < 4; e++) oacc[nt][e] = 0.0f;
    float m_prev = -CUDART_INF_F, l_run = 0.0f;
    const int qrow = (warp & 3) * 32 + lane;   // softmax row for warps 0-3
    const int arow = warp * 16;                // PV rows for all warps
    int phA[2] = { 0, 0 };

    for (int j = 0; j <= jmax; j++) {
        const int scur = j & 1;
        const int k0 = j * 64;
        const uint32_t vst = sb + ASM_V + (uint32_t)scur * ASM_V_STAGE;

        // 1. wait S_j  (K stage scur now reusable)
        mbar_wait(sb + 8 + 8 * scur, phA[scur]);
        phA[scur] ^= 1;

        // 2. EARLY K prefetch: K_{j+2} into K stage scur (full-iter latency)
        const bool kpre = (j + 2 <= jmax);
        if (kpre) {
            atc_load_k(sb + ASM_K + (uint32_t)scur * ASM_K_STAGE,
                       kh_g, kl_g, (j + 2) * 64, tid);
            CPCOMMIT();
        }

        // 3. warps 0-3: LDTM S
        float sv[64];
        if (warp < 4) {
            asm volatile("tcgen05.fence::after_thread_sync;" ::: "memory");
            uint32_t sr[64];
            TCLD_X32(sr, tmem + scur * 64);
            TCLD_X32(sr + 32, tmem + scur * 64 + 32);
            asm volatile("tcgen05.wait::ld.sync.aligned;" ::: "memory");
            asm volatile("tcgen05.fence::before_thread_sync;" ::: "memory");
#pragma unroll
            for (int c = 0; c < 64; c++) sv[c] = __uint_as_float(sr[c]);
        }
        __syncthreads();

        // 4. ensure K_{j+1} resident; issue S_{j+1}.  At j==jmax ensure V_j.
        if (j < jmax) {
            // pending allowed: V_{j+1} (always issued) + K_{j+2} (if kpre)
            if (kpre) { asm volatile("cp.async.wait_group 2;" ::: "memory"); }
            else      { asm volatile("cp.async.wait_group 1;" ::: "memory"); }
            __syncthreads();
            asm volatile("fence.proxy.async.shared::cta;" ::: "memory");
            if (warp == 4 && elect1()) {
                asm volatile("tcgen05.fence::after_thread_sync;" ::: "memory");
                issue_S_attn(sb, sb + ASM_K + (uint32_t)((j + 1) & 1) * ASM_K_STAGE,
                             tmem + ((j + 1) & 1) * 64);
                asm volatile(
                    "tcgen05.commit.cta_group::1.mbarrier::arrive::one.shared::cluster.b64 [%0];"
                    :: "r"(sb + 8 + 8 * ((j + 1) & 1)) : "memory");
            }
        } else {
            asm volatile("cp.async.wait_group 0;" ::: "memory");
            __syncthreads();
        }

        // 5. warps 0-3: softmax (per-lane full row), pack P, write alpha
        if (warp < 4) {
            const int grow = q0 + qrow;
            const bool needmask = (j >= 2 * qt);
            float mx = -CUDART_INF_F;
#pragma unroll
            for (int c = 0; c < 64; c++) {
                float v = sv[c] * SCALE_F;
                if (needmask && (k0 + c > grow)) v = -CUDART_INF_F;
                sv[c] = v;
                mx = fmaxf(mx, v);
            }
            float m_new = fmaxf(m_prev, mx);
            float alpha = __expf(m_prev - m_new);
            float sum = 0.0f;
#pragma unroll
            for (int c = 0; c < 64; c++) {
                float p = __expf(sv[c] - m_new);
                sv[c] = p;
                sum += p;
            }
            l_run = l_run * alpha + sum;
            m_prev = m_new;
            alphaArr[qrow] = alpha;
#pragma unroll
            for (int c8 = 0; c8 < 8; c8++) {
                uint32_t hh[4], ll[4];
#pragma unroll
                for (int q = 0; q < 4; q++)
                    split_pack2(sv[c8 * 8 + 2 * q], sv[c8 * 8 + 2 * q + 1],
                                hh[q], ll[q]);
                STS128(sb + ASM_PH + APSW(qrow, c8), hh[0], hh[1], hh[2], hh[3]);
                STS128(sb + ASM_PL + APSW(qrow, c8), ll[0], ll[1], ll[2], ll[3]);
            }
        }
        __syncthreads();

        // 6. PV (all 8 warps): rescale + P·V from V stage scur
        {
            float a0 = alphaArr[arow + (lane >> 2)];
            float a1 = alphaArr[arow + 8 + (lane >> 2)];
#pragma unroll
            for (int nt = 0; nt < 16; nt++) {
                oacc[nt][0] *= a0; oacc[nt][1] *= a0;
                oacc[nt][2] *= a1; oacc[nt][3] *= a1;
            }
            const uint32_t vbh = vst;
            const uint32_t vbl = vst + 16384;
#pragma unroll
            for (int s2 = 0; s2 < 4; s2++) {
                uint32_t pah[4], pal[4];
                LDSM4(pah, sb + ASM_PH + APSW(arow + (lane & 15), 2 * s2 + (lane >> 4)));
                LDSM4(pal, sb + ASM_PL + APSW(arow + (lane & 15), 2 * s2 + (lane >> 4)));
#pragma unroll
                for (int np = 0; np < 8; np++) {
                    uint32_t vh4[4], vl4[4];
                    int vrow = s2 * 16 + (lane & 7) + (((lane >> 3) & 1) << 3);
                    int vch  = 2 * np + (lane >> 4);
                    LDSM4T(vh4, vbh + SOFF2(vrow, vch));
                    LDSM4T(vl4, vbl + SOFF2(vrow, vch));
                    MMA_BF16(oacc[2 * np],     pah, vh4 + 0);
                    MMA_BF16(oacc[2 * np],     pah, vl4 + 0);
                    MMA_BF16(oacc[2 * np],     pal, vh4 + 0);
                    MMA_BF16(oacc[2 * np + 1], pah, vh4 + 2);
                    MMA_BF16(oacc[2 * np + 1], pah, vl4 + 2);
                    MMA_BF16(oacc[2 * np + 1], pal, vh4 + 2);
                }
            }
        }

        // 7. V prefetch: V_{j+2} into V stage scur (all PV reads done)
        if (j + 2 <= jmax) {
            __syncthreads();
            atc_load_v(vst, vh_g, vl_g, (j + 2) * 64, tid);
            CPCOMMIT();
        }
    }

    // epilogue: invl via smem, scale + split-store
    __syncthreads();
    if (warp < 4) alphaArr[qrow] = 1.0f / l_run;
    __syncthreads();
    {
        float inv0 = alphaArr[arow + (lane >> 2)];
        float inv1 = alphaArr[arow + 8 + (lane >> 2)];
        __nv_bfloat16* ch = Chi + rowbase;
        __nv_bfloat16* cl = Clo + rowbase;
#pragma unroll
        for (int nt = 0; nt < 16; nt++) {
            int c0 = nt * 8 + (lane & 3) * 2;
            size_t i0 = (size_t)(q0 + arow + (lane >> 2)) * Ddim + c0;
            size_t i1 = i0 + (size_t)8 * Ddim;
            store_split2(&ch[i0], &cl[i0], oacc[nt][0] * inv0, oacc[nt][1] * inv0);
            store_split2(&ch[i1], &cl[i1], oacc[nt][2] * inv1, oacc[nt][3] * inv1);
        }
    }
    __syncthreads();
    if (warp == 0) {
        asm volatile("tcgen05.relinquish_alloc_permit.cta_group::1.sync.aligned;");
        asm volatile("tcgen05.dealloc.cta_group::1.sync.aligned.b32 %0, %1;"
                     :: "r"(tmem), "r"(128u));
    }

#else
    // =====================================================================
    // mma.sync fallback (validated R5-R9)
    // =====================================================================
    const int arow = warp * 16;
    {
        const __nv_bfloat16* gq[2] = { qh_g, ql_g };
#pragma unroll
        for (int a2 = 0; a2 < 2; a2++)
#pragma unroll
            for (int i = 0; i < 8; i++) {
                int u = i * 256 + tid;
                int r = u >> 4, c = u & 15;
                cp16(sb + a2 * 32768 + SOFF2(r, c), gq[a2] + (size_t)r * Ddim + c * 8);
            }
        const __nv_bfloat16* gp0[4] = { kh_g, kl_g, vh_g, vl_g };
#pragma unroll
        for (int a2 = 0; a2 < 4; a2++)
#pragma unroll
            for (int i = 0; i < 4; i++) {
                int u = i * 256 + tid;
                int r = u >> 4, c = u & 15;
                cp16(sb + 65536 + a2 * 16384 + SOFF2(r, c), gp0[a2] + (size_t)r * Ddim + c * 8);
            }
        asm volatile("cp.async.commit_group;" ::: "memory");
#pragma unroll
        for (int a2 = 0; a2 < 4; a2++)
#pragma unroll
            for (int i = 0; i < 4; i++) {
                int u = i * 256 + tid;
                int r = u >> 4, c = u & 15;
                cp16(sb + 65536 + 65536 + a2 * 16384 + SOFF2(r, c),
                     gp0[a2] + (size_t)(64 + r) * Ddim + c * 8);
            }
        asm volatile("cp.async.commit_group;" ::: "memory");
    }
    asm volatile("cp.async.wait_group 1;" ::: "memory");
    __syncthreads();

    uint32_t qfh[8][4];
#pragma unroll
    for (int s = 0; s < 8; s++)
        LDSM4(qfh[s], sb + SOFF2(arow + (lane & 15), 2 * s + (lane >> 4)));

    float oacc[16][4];
#pragma unroll
    for (int nt = 0; nt < 16; nt++)
#pragma unroll
        for (int e = 0; e < 4; e++) oacc[nt][e] = 0.0f;
    float m0 = -CUDART_INF_F, m1 = -CUDART_INF_F, l0 = 0.0f, l1 = 0.0f;
    const int row0 = q0 + arow + (lane >> 2);
    const int row1 = row0 + 8;

    for (int j = 0; j <= jmax; j++) {
        if (j > 0) {
            if (j < jmax) { asm volatile("cp.async.wait_group 1;" ::: "memory"); }
            else          { asm volatile("cp.async.wait_group 0;" ::: "memory"); }
            __syncthreads();
        }
        const uint32_t kbase = sb + 65536 + (uint32_t)(j & 1) * 65536;
        const int k0 = j * 64;

        float sacc[8][4];
#pragma unroll
        for (int nt = 0; nt < 8; nt++)
#pragma unroll
            for (int e = 0; e < 4; e++) sacc[nt][e] = 0.0f;

#pragma unroll
        for (int s = 0; s < 8; s++) {
            uint32_t ql4[4];
            LDSM4(ql4, sb + 32768 + SOFF2(arow + (lane & 15), 2 * s + (lane >> 4)));
#pragma unroll
            for (int np = 0; np < 4; np++) {
                uint32_t kh4[4], kl4[4];
                int krow = np * 16 + (lane & 7) + ((lane >> 4) << 3);
                int kch  = 2 * s + ((lane >> 3) & 1);
                LDSM4(kh4, kbase + SOFF2(krow, kch));
                LDSM4(kl4, kbase + 16384 + SOFF2(krow, kch));
                MMA_BF16(sacc[2 * np],     qfh[s], kh4 + 0);
                MMA_BF16(sacc[2 * np],     qfh[s], kl4 + 0);
                MMA_BF16(sacc[2 * np],     ql4,    kh4 + 0);
                MMA_BF16(sacc[2 * np + 1], qfh[s], kh4 + 2);
                MMA_BF16(sacc[2 * np + 1], qfh[s], kl4 + 2);
                MMA_BF16(sacc[2 * np + 1], ql4,    kh4 + 2);
            }
        }

        const bool diag = (k0 + 63 > q0 + arow);
        float mx0 = -CUDART_INF_F, mx1 = -CUDART_INF_F;
#pragma unroll
        for (int nt = 0; nt < 8; nt++) {
            float v0 = sacc[nt][0] * SCALE_F;
            float v1 = sacc[nt][1] * SCALE_F;
            float v2 = sacc[nt][2] * SCALE_F;
            float v3 = sacc[nt][3] * SCALE_F;
            if (diag) {
                int colb = k0 + nt * 8 + ((lane & 3) << 1);
                if (colb     > row0) v0 = -CUDART_INF_F;
                if (colb + 1 > row0) v1 = -CUDART_INF_F;
                if (colb     > row1) v2 = -CUDART_INF_F;
                if (colb + 1 > row1) v3 = -CUDART_INF_F;
            }
            sacc[nt][0] = v0; sacc[nt][1] = v1; sacc[nt][2] = v2; sacc[nt][3] = v3;
            mx0 = fmaxf(mx0, fmaxf(v0, v1));
            mx1 = fmaxf(mx1, fmaxf(v2, v3));
        }
        mx0 = fmaxf(mx0, __shfl_xor_sync(0xffffffffu, mx0, 1));
        mx0 = fmaxf(mx0, __shfl_xor_sync(0xffffffffu, mx0, 2));
        mx1 = fmaxf(mx1, __shfl_xor_sync(0xffffffffu, mx1, 1));
        mx1 = fmaxf(mx1, __shfl_xor_sync(0xffffffffu, mx1, 2));

        float mn0 = fmaxf(m0, mx0), mn1 = fmaxf(m1, mx1);
        float a0 = __expf(m0 - mn0), a1 = __expf(m1 - mn1);
        float s0 = 0.0f, s1 = 0.0f;
#pragma unroll
        for (int nt = 0; nt < 8; nt++) {
            float p0 = __expf(sacc[nt][0] - mn0);
            float p1 = __expf(sacc[nt][1] - mn0);
            float p2 = __expf(sacc[nt][2] - mn1);
            float p3 = __expf(sacc[nt][3] - mn1);
            sacc[nt][0] = p0; sacc[nt][1] = p1; sacc[nt][2] = p2; sacc[nt][3] = p3;
            s0 += p0 + p1;
            s1 += p2 + p3;
        }
        s0 += __shfl_xor_sync(0xffffffffu, s0, 1);
        s0 += __shfl_xor_sync(0xffffffffu, s0, 2);
        s1 += __shfl_xor_sync(0xffffffffu, s1, 1);
        s1 += __shfl_xor_sync(0xffffffffu, s1, 2);
        l0 = l0 * a0 + s0;
        l1 = l1 * a1 + s1;
        m0 = mn0; m1 = mn1;
#pragma unroll
        for (int nt = 0; nt < 16; nt++) {
            oacc[nt][0] *= a0; oacc[nt][1] *= a0;
            oacc[nt][2] *= a1; oacc[nt][3] *= a1;
        }

        uint32_t pah[4][4], pal[4][4];
#pragma unroll
        for (int s2 = 0; s2 < 4; s2++) {
            split_pack2(sacc[2 * s2][0],     sacc[2 * s2][1],     pah[s2][0], pal[s2][0]);
            split_pack2(sacc[2 * s2][2],     sacc[2 * s2][3],     pah[s2][1], pal[s2][1]);
            split_pack2(sacc[2 * s2 + 1][0], sacc[2 * s2 + 1][1], pah[s2][2], pal[s2][2]);
            split_pack2(sacc[2 * s2 + 1][2], sacc[2 * s2 + 1][3], pah[s2][3], pal[s2][3]);
        }

#pragma unroll
        for (int s2 = 0; s2 < 4; s2++) {
#pragma unroll
            for (int np = 0; np < 8; np++) {
                uint32_t vh4[4], vl4[4];
                int vrow = s2 * 16 + (lane & 7) + (((lane >> 3) & 1) << 3);
                int vch  = 2 * np + (lane >> 4);
                LDSM4T(vh4, kbase + 32768 + SOFF2(vrow, vch));
                LDSM4T(vl4, kbase + 49152 + SOFF2(vrow, vch));
                MMA_BF16(oacc[2 * np],     pah[s2], vh4 + 0);
                MMA_BF16(oacc[2 * np],     pah[s2], vl4 + 0);
                MMA_BF16(oacc[2 * np],     pal[s2], vh4 + 0);
                MMA_BF16(oacc[2 * np + 1], pah[s2], vh4 + 2);
                MMA_BF16(oacc[2 * np + 1], pah[s2], vl4 + 2);
                MMA_BF16(oacc[2 * np + 1], pal[s2], vh4 + 2);
            }
        }

        __syncthreads();
        if (j + 2 <= jmax) {
            size_t off = (size_t)(j + 2) * 64 * Ddim;
            const __nv_bfloat16* gp2[4] = { kh_g + off, kl_g + off, vh_g + off, vl_g + off };
#pragma unroll
            for (int a2 = 0; a2 < 4; a2++)
#pragma unroll
                for (int i = 0; i < 4; i++) {
                    int u = i * 256 + tid;
                    int r = u >> 4, c = u & 15;
                    cp16(sb + 65536 + (uint32_t)(j & 1) * 65536 + a2 * 16384 + SOFF2(r, c),
                         gp2[a2] + (size_t)r * Ddim + c * 8);
                }
            asm volatile("cp.async.commit_group;" ::: "memory");
        }
    }

    float inv0 = 1.0f / l0, inv1 = 1.0f / l1;
    __nv_bfloat16* ch = Chi + rowbase;
    __nv_bfloat16* cl = Clo + rowbase;
#pragma unroll
    for (int nt = 0; nt < 16; nt++) {
        int c0 = nt * 8 + (lane & 3) * 2;
        size_t i0 = (size_t)(q0 + arow + (lane >> 2)) * Ddim + c0;
        size_t i1 = i0 + (size_t)8 * Ddim;
        store_split2(&ch[i0], &cl[i0], oacc[nt][0] * inv0, oacc[nt][1] * inv0);
        store_split2(&ch[i1], &cl[i1], oacc[nt][2] * inv1, oacc[nt][3] * inv1);
    }
#endif  // GEMM_TCGEN05
}

// ---------------------------------------------------------------------------
extern "C" void kernel_launch(void* const* d_in, const int* in_sizes, int n_in,
                              void* d_out, int out_size)
{
    const float* x  = (const float*)d_in[0];
    const float* Wq = (const float*)d_in[1];
    const float* Wk = (const float*)d_in[2];
    const float* Wv = (const float*)d_in[3];
    const float* Wo = (const float*)d_in[4];
    float* out = (float*)d_out;

    __nv_bfloat16 *xhi, *xlo, *whi, *wlo, *qkvhi, *qkvlo, *chi, *clo;
    cudaGetSymbolAddress((void**)&xhi, g_xhi);
    cudaGetSymbolAddress((void**)&xlo, g_xlo);
    cudaGetSymbolAddress((void**)&whi, g_whi);
    cudaGetSymbolAddress((void**)&wlo, g_wlo);
    cudaGetSymbolAddress((void**)&qkvhi, g_qkvhi);
    cudaGetSymbolAddress((void**)&qkvlo, g_qkvlo);
    cudaGetSymbolAddress((void**)&chi, g_chi);
    cudaGetSymbolAddress((void**)&clo, g_clo);

    const size_t DD = (size_t)Ddim * Ddim;
    const size_t MD = (size_t)MROWS * Ddim;

    // one fused split launch (8 floats/thread)
    const int total8 = XN8 + 4 * WN8;
    split_all<<<total8 / 256, 256>>>(x, Wq, Wk, Wv, Wo, xhi, xlo, whi, wlo);

    cudaFuncSetAttribute(gemm_any, cudaFuncAttributeMaxDynamicSharedMemorySize,
                         GSMEM_UNIFIED);

    // fused Q/K/V projections -> bf16 hi/lo split outputs (256x256 tiles)
    dim3 gqkv(Ddim / 256, MROWS / 256, 3);   // (8, 16, 3)
    gemm_any<<<gqkv, 256, GSMEM_UNIFIED>>>(xhi, xlo, whi, wlo, DD,
                                           qkvhi, qkvlo, MD, nullptr,
                                           MROWS, Ddim, Ddim);

    // attention -> ctx bf16 hi/lo split
    cudaFuncSetAttribute(attn_any, cudaFuncAttributeMaxDynamicSharedMemorySize,
                         ASMEM_TOTAL);
    dim3 ga(Sdim / 128, Bdim * Hdim);   // (8, 64)
    attn_any<<<ga, 256, ASMEM_TOTAL>>>(qkvhi, qkvlo, qkvhi + MD, qkvlo + MD,
                                       qkvhi + 2 * MD, qkvlo + 2 * MD, chi, clo);

    // output projection -> fp32 out
    dim3 go(Ddim / 256, MROWS / 256, 1);   // (8, 16)
    gemm_any<<<go, 256, GSMEM_UNIFIED>>>(chi, clo, whi + 3 * DD, wlo + 3 * DD, 0,
                                         nullptr, nullptr, 0, out,
                                         MROWS, Ddim, Ddim);
}